// round 1
// baseline (speedup 1.0000x reference)
#include <cuda_runtime.h>
#include <math.h>

#define NB 4
#define SS 1024
#define DD 1024
#define NH 16
#define DKH 64
#define MT (NB*SS)   // 4096 rows

// Scratch (allocation-free rule: __device__ globals)
__device__ float g_q[MT*DD];
__device__ float g_k[MT*DD];
__device__ float g_v[MT*DD];
__device__ float g_attn[MT*DD];

// ---------------------------------------------------------------------------
// GEMM body: C[M,1024] = A[M,1024] @ W[1024,1024] + bias
// 128x128 block tile, BK=16, 256 threads, 8x8 micro-tile per thread.
// ---------------------------------------------------------------------------
__device__ __forceinline__ void gemm_body(
    const float* __restrict__ A, const float* __restrict__ W,
    const float* __restrict__ bias, float* __restrict__ C,
    float As[16][132], float Bs[16][132])
{
    const int tid = threadIdx.x;
    const int bm = blockIdx.y * 128;
    const int bn = blockIdx.x * 128;
    const int tx = tid & 15, ty = tid >> 4;
    const int a_m = tid >> 2;            // 0..63
    const int a_k = (tid & 3) << 2;      // 0,4,8,12
    const int b_k = tid >> 5;            // 0..7
    const int b_n = (tid & 31) << 2;     // 0..124

    float acc[8][8];
#pragma unroll
    for (int i = 0; i < 8; i++)
#pragma unroll
        for (int j = 0; j < 8; j++) acc[i][j] = 0.0f;

    for (int k0 = 0; k0 < 1024; k0 += 16) {
#pragma unroll
        for (int r = 0; r < 2; r++) {
            float4 av = *(const float4*)&A[(size_t)(bm + a_m + r*64)*1024 + k0 + a_k];
            As[a_k+0][a_m + r*64] = av.x;
            As[a_k+1][a_m + r*64] = av.y;
            As[a_k+2][a_m + r*64] = av.z;
            As[a_k+3][a_m + r*64] = av.w;
        }
#pragma unroll
        for (int r = 0; r < 2; r++) {
            *(float4*)&Bs[b_k + r*8][b_n] =
                *(const float4*)&W[(size_t)(k0 + b_k + r*8)*1024 + bn + b_n];
        }
        __syncthreads();
#pragma unroll
        for (int kk = 0; kk < 16; kk++) {
            float a[8], bb[8];
            *(float4*)&a[0]  = *(const float4*)&As[kk][ty*8];
            *(float4*)&a[4]  = *(const float4*)&As[kk][ty*8+4];
            *(float4*)&bb[0] = *(const float4*)&Bs[kk][tx*8];
            *(float4*)&bb[4] = *(const float4*)&Bs[kk][tx*8+4];
#pragma unroll
            for (int i = 0; i < 8; i++)
#pragma unroll
                for (int j = 0; j < 8; j++)
                    acc[i][j] += a[i] * bb[j];
        }
        __syncthreads();
    }

#pragma unroll
    for (int i = 0; i < 8; i++) {
        int row = bm + ty*8 + i;
#pragma unroll
        for (int j = 0; j < 8; j += 4) {
            int col = bn + tx*8 + j;
            float4 o;
            o.x = acc[i][j+0] + bias[col+0];
            o.y = acc[i][j+1] + bias[col+1];
            o.z = acc[i][j+2] + bias[col+2];
            o.w = acc[i][j+3] + bias[col+3];
            *(float4*)&C[(size_t)row*1024 + col] = o;
        }
    }
}

// Fused Q/K/V projections: blockIdx.z in {0,1,2} selects the problem.
__global__ __launch_bounds__(256) void qkv_gemm_kernel(
    const float* __restrict__ q, const float* __restrict__ k, const float* __restrict__ v,
    const float* __restrict__ Wq, const float* __restrict__ bq,
    const float* __restrict__ Wk, const float* __restrict__ bk,
    const float* __restrict__ Wv, const float* __restrict__ bv)
{
    __shared__ float As[16][132];
    __shared__ float Bs[16][132];
    const float *A, *W, *bias;
    float* C;
    if (blockIdx.z == 0)      { A = q; W = Wq; bias = bq; C = g_q; }
    else if (blockIdx.z == 1) { A = k; W = Wk; bias = bk; C = g_k; }
    else                      { A = v; W = Wv; bias = bv; C = g_v; }
    gemm_body(A, W, bias, C, As, Bs);
}

__global__ __launch_bounds__(256) void out_gemm_kernel(
    const float* __restrict__ Wo, const float* __restrict__ bo, float* __restrict__ out)
{
    __shared__ float As[16][132];
    __shared__ float Bs[16][132];
    gemm_body(g_attn, Wo, bo, out, As, Bs);
}

// ---------------------------------------------------------------------------
// RoPE. IMPORTANT: reference reshapes (B,S,H,dk)->(B*H,S,dk) WITHOUT permute,
// so the effective position is pos = (s*H + h) mod S.
// One thread per (b,s,h,pair). Double trig for accuracy regardless of
// fast-math flags (args up to ~1023 rad).
// ---------------------------------------------------------------------------
__global__ __launch_bounds__(256) void rope_kernel(float* __restrict__ q, float* __restrict__ k)
{
    int idx = blockIdx.x * 256 + threadIdx.x;       // B*S*H*32 = 2097152 pairs
    int i = idx & 31;
    int h = (idx >> 5) & 15;
    int s = (idx >> 9) & 1023;
    int b = idx >> 19;
    int pos = (s * 16 + h) & 1023;
    const double LOG1E4 = 9.210340371976184;        // log(10000)
    double inv = exp(-((double)i / 32.0) * LOG1E4);
    double ang = (double)pos * inv;
    float c  = (float)cos(ang);
    float sn = (float)sin(ang);
    size_t base = ((size_t)(b * 1024 + s)) * 1024 + h * 64 + 2 * i;
    float q0 = q[base], q1 = q[base + 1];
    q[base]     = q0 * c - q1 * sn;
    q[base + 1] = q0 * sn + q1 * c;
    float k0 = k[base], k1 = k[base + 1];
    k[base]     = k0 * c - k1 * sn;
    k[base + 1] = k0 * sn + k1 * c;
}

// ---------------------------------------------------------------------------
// Flash attention: grid (S/64, H, B), 256 threads.
// smem: Qs transposed [d][r], KP = K transposed [d][c] (reused as P[r][c]),
// Vs [c][d]. 3 * 16KB = 48KB static.
// Thread (r0=(tid>>4)*4, c0=(tid&15)*4) owns a 4x4 micro-tile.
// ---------------------------------------------------------------------------
__global__ __launch_bounds__(256) void attn_kernel(
    const float* __restrict__ Q, const float* __restrict__ K,
    const float* __restrict__ V, float* __restrict__ O)
{
    __shared__ float Qs[64 * 64];
    __shared__ float KP[64 * 64];
    __shared__ float Vs[64 * 64];

    const int tid = threadIdx.x;
    const int h = blockIdx.y, b = blockIdx.z;
    const int q0 = blockIdx.x * 64;
    const int lr = tid >> 2;           // load row 0..63
    const int ld = (tid & 3) << 4;     // load col base {0,16,32,48}
    const int r0 = (tid >> 4) << 2;    // compute row base
    const int c0 = (tid & 15) << 2;    // compute col base
    const float scale = 0.125f;        // 1/sqrt(64)

    // Load Q tile transposed: Qs[d][r]
    {
        const float* qg = Q + ((size_t)(b * SS + q0 + lr)) * DD + h * DKH + ld;
#pragma unroll
        for (int j = 0; j < 16; j += 4) {
            float4 v4 = *(const float4*)&qg[j];
            Qs[(ld + j + 0) * 64 + lr] = v4.x;
            Qs[(ld + j + 1) * 64 + lr] = v4.y;
            Qs[(ld + j + 2) * 64 + lr] = v4.z;
            Qs[(ld + j + 3) * 64 + lr] = v4.w;
        }
    }

    float m[4], l[4], acc[4][4];
#pragma unroll
    for (int i = 0; i < 4; i++) {
        m[i] = -1e30f; l[i] = 0.0f;
#pragma unroll
        for (int j = 0; j < 4; j++) acc[i][j] = 0.0f;
    }

    for (int kt = 0; kt < 16; kt++) {
        __syncthreads();   // previous PV done before overwriting KP/Vs
        {
            const float* kg = K + ((size_t)(b * SS + kt * 64 + lr)) * DD + h * DKH + ld;
            const float* vg = V + ((size_t)(b * SS + kt * 64 + lr)) * DD + h * DKH + ld;
#pragma unroll
            for (int j = 0; j < 16; j += 4) {
                float4 v4 = *(const float4*)&kg[j];
                KP[(ld + j + 0) * 64 + lr] = v4.x;
                KP[(ld + j + 1) * 64 + lr] = v4.y;
                KP[(ld + j + 2) * 64 + lr] = v4.z;
                KP[(ld + j + 3) * 64 + lr] = v4.w;
                *(float4*)&Vs[lr * 64 + ld + j] = *(const float4*)&vg[j];
            }
        }
        __syncthreads();

        // Scores micro-tile: s[i][j] = Q[r0+i] . K[c0+j]
        float s[4][4];
#pragma unroll
        for (int i = 0; i < 4; i++)
#pragma unroll
            for (int j = 0; j < 4; j++) s[i][j] = 0.0f;
#pragma unroll 8
        for (int d = 0; d < 64; d++) {
            float a[4], bb[4];
            *(float4*)a  = *(const float4*)&Qs[d * 64 + r0];
            *(float4*)bb = *(const float4*)&KP[d * 64 + c0];
#pragma unroll
            for (int i = 0; i < 4; i++)
#pragma unroll
                for (int j = 0; j < 4; j++)
                    s[i][j] += a[i] * bb[j];
        }

        // Online softmax per row (16 threads/row group; shfl widths stay in 16-lane half)
#pragma unroll
        for (int i = 0; i < 4; i++) {
            float tmax = -1e30f;
#pragma unroll
            for (int j = 0; j < 4; j++) { s[i][j] *= scale; tmax = fmaxf(tmax, s[i][j]); }
#pragma unroll
            for (int off = 8; off >= 1; off >>= 1)
                tmax = fmaxf(tmax, __shfl_xor_sync(0xffffffffu, tmax, off));
            float nm = fmaxf(m[i], tmax);
            float corr = __expf(m[i] - nm);
            float ps = 0.0f;
#pragma unroll
            for (int j = 0; j < 4; j++) { s[i][j] = __expf(s[i][j] - nm); ps += s[i][j]; }
#pragma unroll
            for (int off = 8; off >= 1; off >>= 1)
                ps += __shfl_xor_sync(0xffffffffu, ps, off);
            l[i] = l[i] * corr + ps;
            m[i] = nm;
#pragma unroll
            for (int j = 0; j < 4; j++) acc[i][j] *= corr;
        }

        __syncthreads();   // everyone finished reading KP (scores)
        // Write P into KP buffer, layout [r][c]
#pragma unroll
        for (int i = 0; i < 4; i++)
#pragma unroll
            for (int j = 0; j < 4; j++)
                KP[(r0 + i) * 64 + c0 + j] = s[i][j];
        __syncthreads();

        // PV: acc[i][jj] += P[r0+i][j] * V[j][c0+jj]
#pragma unroll 8
        for (int j = 0; j < 64; j++) {
            float vv[4];
            *(float4*)vv = *(const float4*)&Vs[j * 64 + c0];
            float p0 = KP[(r0 + 0) * 64 + j];
            float p1 = KP[(r0 + 1) * 64 + j];
            float p2 = KP[(r0 + 2) * 64 + j];
            float p3 = KP[(r0 + 3) * 64 + j];
#pragma unroll
            for (int jj = 0; jj < 4; jj++) {
                acc[0][jj] += p0 * vv[jj];
                acc[1][jj] += p1 * vv[jj];
                acc[2][jj] += p2 * vv[jj];
                acc[3][jj] += p3 * vv[jj];
            }
        }
    }

    // Normalize and write out: O[(b,q0+r0+i), h*64 + c0..c0+3]
#pragma unroll
    for (int i = 0; i < 4; i++) {
        float inv = 1.0f / l[i];
        float4 o;
        o.x = acc[i][0] * inv;
        o.y = acc[i][1] * inv;
        o.z = acc[i][2] * inv;
        o.w = acc[i][3] * inv;
        *(float4*)&O[((size_t)(b * SS + q0 + r0 + i)) * DD + h * DKH + c0] = o;
    }
}

// ---------------------------------------------------------------------------
extern "C" void kernel_launch(void* const* d_in, const int* in_sizes, int n_in,
                              void* d_out, int out_size)
{
    const float* q  = (const float*)d_in[0];
    const float* k  = (const float*)d_in[1];
    const float* v  = (const float*)d_in[2];
    const float* Wq = (const float*)d_in[3];
    const float* bq = (const float*)d_in[4];
    const float* Wk = (const float*)d_in[5];
    const float* bk = (const float*)d_in[6];
    const float* Wv = (const float*)d_in[7];
    const float* bv = (const float*)d_in[8];
    const float* Wo = (const float*)d_in[9];
    const float* bo = (const float*)d_in[10];
    float* out = (float*)d_out;

    float* gq; cudaGetSymbolAddress((void**)&gq, g_q);
    float* gk; cudaGetSymbolAddress((void**)&gk, g_k);
    float* gv; cudaGetSymbolAddress((void**)&gv, g_v);
    float* ga; cudaGetSymbolAddress((void**)&ga, g_attn);

    // 1) Fused QKV projections
    dim3 ggrid(1024 / 128, MT / 128, 3);
    qkv_gemm_kernel<<<ggrid, 256>>>(q, k, v, Wq, bq, Wk, bk, Wv, bv);

    // 2) RoPE on Q and K in place
    rope_kernel<<<(NB * SS * NH * 32) / 256, 256>>>(gq, gk);

    // 3) Attention
    dim3 agrid(SS / 64, NH, NB);
    attn_kernel<<<agrid, 256>>>(gq, gk, gv, ga);

    // 4) Output projection
    dim3 ogrid(1024 / 128, MT / 128, 1);
    out_gemm_kernel<<<ogrid, 256>>>(Wo, bo, out);
}

// round 10
// speedup vs baseline: 1.1041x; 1.1041x over previous
#include <cuda_runtime.h>
#include <stdint.h>
#include <math.h>

#define NB 4
#define SS 1024
#define DD 1024
#define NH 16
#define DKH 64
#define MT (NB*SS)   // 4096 rows

// Scratch (allocation-free rule: __device__ globals)
__device__ float g_q[MT*DD];
__device__ float g_k[MT*DD];
__device__ float g_v[MT*DD];
__device__ float g_attn[MT*DD];
__device__ float2 g_rope[1024*32];   // [pos][freq] -> (cos, sin)

// ---------------------------------------------------------------------------
// cp.async helpers
// ---------------------------------------------------------------------------
__device__ __forceinline__ void cp16(void* s, const void* g) {
    unsigned int sa = (unsigned int)__cvta_generic_to_shared(s);
    asm volatile("cp.async.ca.shared.global [%0], [%1], 16;\n" :: "r"(sa), "l"(g));
}
__device__ __forceinline__ void cp_commit() { asm volatile("cp.async.commit_group;\n"); }
__device__ __forceinline__ void cp_wait0()  { asm volatile("cp.async.wait_group 0;\n"); }

// ---------------------------------------------------------------------------
// RoPE table: pos in [0,1024), freq i in [0,32). Double trig for accuracy
// (args up to ~1023 rad; immune to --use_fast_math).
// ---------------------------------------------------------------------------
__global__ __launch_bounds__(256) void rope_table_kernel(float2* __restrict__ tab)
{
    int idx = blockIdx.x * 256 + threadIdx.x;   // 32768
    int i = idx & 31;
    int pos = idx >> 5;
    const double LOG1E4 = 9.210340371976184;    // log(10000)
    double inv = exp(-((double)i / 32.0) * LOG1E4);
    double ang = (double)pos * inv;
    tab[idx] = make_float2((float)cos(ang), (float)sin(ang));
}

// ---------------------------------------------------------------------------
// GEMM body: C[M,1024] = A[M,1024] @ W[1024,1024] + bias, optional fused RoPE.
// 128x128 tile, BK=16, 256 threads, 8x8 micro-tile, 2-stage cp.async pipeline.
// As row-major [128][16] (scalar broadcast a-loads), Bs [16][128].
// Static smem only (32 KB).
// ---------------------------------------------------------------------------
__device__ __forceinline__ void gemm_body(
    const float* __restrict__ A, const float* __restrict__ W,
    const float* __restrict__ bias, float* __restrict__ C,
    const float2* __restrict__ rope, int do_rope,
    float* As /*[2][128*16]*/, float* Bs /*[2][16*128]*/)
{
    const int tid = threadIdx.x;
    const int bm = blockIdx.y * 128;
    const int bn = blockIdx.x * 128;
    const int tx = tid & 15, ty = tid >> 4;

    // copy indices
    const int am  = tid >> 1;          // 0..127 (A row)
    const int ak  = (tid & 1) * 8;     // 0 or 8 (A float col within 16)
    const int bkk = tid >> 4;          // 0..15 (B row)
    const int bn8 = (tid & 15) * 8;    // 0..120 (B float col)

    const float* Abase = A + (size_t)(bm + am) * 1024 + ak;
    const float* Wbase = W + (size_t)bkk * 1024 + bn + bn8;

    // stage 0
    {
        float* asd = As + am * 16 + ak;
        cp16(asd,     Abase);
        cp16(asd + 4, Abase + 4);
        float* bsd = Bs + bkk * 128 + bn8;
        cp16(bsd,     Wbase);
        cp16(bsd + 4, Wbase + 4);
        cp_commit();
    }

    float acc[8][8];
#pragma unroll
    for (int i = 0; i < 8; i++)
#pragma unroll
        for (int j = 0; j < 8; j++) acc[i][j] = 0.0f;

    for (int it = 0; it < 64; ++it) {
        cp_wait0();
        __syncthreads();
        if (it + 1 < 64) {
            int nb = (it + 1) & 1;
            int k0 = (it + 1) * 16;
            float* asd = As + nb * (128 * 16) + am * 16 + ak;
            cp16(asd,     Abase + k0);
            cp16(asd + 4, Abase + k0 + 4);
            float* bsd = Bs + nb * (16 * 128) + bkk * 128 + bn8;
            cp16(bsd,     Wbase + (size_t)k0 * 1024);
            cp16(bsd + 4, Wbase + (size_t)k0 * 1024 + 4);
            cp_commit();
        }
        const float* as = As + (it & 1) * (128 * 16);
        const float* bs = Bs + (it & 1) * (16 * 128);
#pragma unroll
        for (int kk = 0; kk < 16; kk++) {
            float a[8], bb[8];
#pragma unroll
            for (int i = 0; i < 8; i++)
                a[i] = as[(ty * 8 + i) * 16 + kk];
            *(float4*)&bb[0] = *(const float4*)&bs[kk * 128 + tx * 8];
            *(float4*)&bb[4] = *(const float4*)&bs[kk * 128 + tx * 8 + 4];
#pragma unroll
            for (int i = 0; i < 8; i++)
#pragma unroll
                for (int j = 0; j < 8; j++)
                    acc[i][j] += a[i] * bb[j];
        }
    }

    // epilogue: bias (+ fused rope for Q/K projections)
    float bias8[8];
    *(float4*)&bias8[0] = *(const float4*)&bias[bn + tx * 8];
    *(float4*)&bias8[4] = *(const float4*)&bias[bn + tx * 8 + 4];

    const int colbase = bn + tx * 8;
    const int hh = colbase >> 6;                 // head of this 8-col chunk
    const int ipb = (colbase & 63) >> 1;         // freq index base

#pragma unroll
    for (int i = 0; i < 8; i++) {
        int row = bm + ty * 8 + i;
        float o[8];
        if (do_rope) {
            int pos = (((row & 1023) * 16 + hh) & 1023);
            const float2* rp = rope + pos * 32 + ipb;
#pragma unroll
            for (int t = 0; t < 4; t++) {
                float2 cs = rp[t];
                float x0 = acc[i][2 * t]     + bias8[2 * t];
                float x1 = acc[i][2 * t + 1] + bias8[2 * t + 1];
                o[2 * t]     = x0 * cs.x - x1 * cs.y;
                o[2 * t + 1] = x0 * cs.y + x1 * cs.x;
            }
        } else {
#pragma unroll
            for (int j = 0; j < 8; j++) o[j] = acc[i][j] + bias8[j];
        }
        *(float4*)&C[(size_t)row * 1024 + colbase]     = *(float4*)&o[0];
        *(float4*)&C[(size_t)row * 1024 + colbase + 4] = *(float4*)&o[4];
    }
}

__global__ __launch_bounds__(256) void qkv_gemm_kernel(
    const float* __restrict__ q, const float* __restrict__ k, const float* __restrict__ v,
    const float* __restrict__ Wq, const float* __restrict__ bq,
    const float* __restrict__ Wk, const float* __restrict__ bk,
    const float* __restrict__ Wv, const float* __restrict__ bv,
    const float2* __restrict__ rope)
{
    __shared__ float As[2 * 128 * 16];
    __shared__ float Bs[2 * 16 * 128];
    const float *A, *W, *bias;
    float* C;
    int do_rope = 1;
    if (blockIdx.z == 0)      { A = q; W = Wq; bias = bq; C = g_q; }
    else if (blockIdx.z == 1) { A = k; W = Wk; bias = bk; C = g_k; }
    else                      { A = v; W = Wv; bias = bv; C = g_v; do_rope = 0; }
    gemm_body(A, W, bias, C, rope, do_rope, As, Bs);
}

__global__ __launch_bounds__(256) void out_gemm_kernel(
    const float* __restrict__ Wo, const float* __restrict__ bo, float* __restrict__ out)
{
    __shared__ float As[2 * 128 * 16];
    __shared__ float Bs[2 * 16 * 128];
    gemm_body(g_attn, Wo, bo, out, (const float2*)0, 0, As, Bs);
}

// ---------------------------------------------------------------------------
// Flash attention: grid (S/64, H, B), 128 threads, STATIC 48KB smem.
// Tiles: 64 q-rows x 64 keys. Micro-tile 8x4 per thread (rg=tid>>4, cg=tid&15).
// smem: Qt[d][r] 64x64 (16KB), KP[d][c] 64x64 (16KB, reused as P[row][key]),
// Vs[c][d] 64x64 (16KB). Scale 1/8 folded into Q load.
// P layout [row][key]: stores conflict-free (consecutive cg lanes), loads
// broadcast (all cg lanes read same row word).
// ---------------------------------------------------------------------------
__global__ __launch_bounds__(128) void attn_kernel(
    const float* __restrict__ Q, const float* __restrict__ K,
    const float* __restrict__ V, float* __restrict__ O)
{
    __shared__ float Qt[64 * 64];
    __shared__ float KP[64 * 64];
    __shared__ float Vs[64 * 64];

    const int tid = threadIdx.x;
    const int h = blockIdx.y, b = blockIdx.z;
    const int q0 = blockIdx.x * 64;
    const int rg = tid >> 4, cg = tid & 15;
    const int r0 = rg * 8, c0 = cg * 4;

    // Load Q tile transposed, pre-scaled by 1/sqrt(64)=0.125
    {
        const int lr = tid >> 1;            // 0..63
        const int dof = (tid & 1) * 32;
        const float* qg = Q + ((size_t)(b * SS + q0 + lr)) * DD + h * DKH + dof;
#pragma unroll
        for (int j = 0; j < 32; j += 4) {
            float4 v4 = *(const float4*)&qg[j];
            Qt[(dof + j + 0) * 64 + lr] = v4.x * 0.125f;
            Qt[(dof + j + 1) * 64 + lr] = v4.y * 0.125f;
            Qt[(dof + j + 2) * 64 + lr] = v4.z * 0.125f;
            Qt[(dof + j + 3) * 64 + lr] = v4.w * 0.125f;
        }
    }

    float m[8], l[8], acc[8][4];
#pragma unroll
    for (int i = 0; i < 8; i++) {
        m[i] = -1e30f; l[i] = 0.0f;
#pragma unroll
        for (int j = 0; j < 4; j++) acc[i][j] = 0.0f;
    }

    const int kr = tid >> 1;            // 0..63
    const int kd = (tid & 1) * 32;

    for (int kt = 0; kt < 16; kt++) {
        __syncthreads();   // prev PV done reading KP/Vs before overwrite
        {
            const float* kg = K + ((size_t)(b * SS + kt * 64 + kr)) * DD + h * DKH + kd;
            const float* vg = V + ((size_t)(b * SS + kt * 64 + kr)) * DD + h * DKH + kd;
#pragma unroll
            for (int j = 0; j < 32; j += 4) {
                float4 kv = *(const float4*)&kg[j];
                KP[(kd + j + 0) * 64 + kr] = kv.x;
                KP[(kd + j + 1) * 64 + kr] = kv.y;
                KP[(kd + j + 2) * 64 + kr] = kv.z;
                KP[(kd + j + 3) * 64 + kr] = kv.w;
                *(float4*)&Vs[kr * 64 + kd + j] = *(const float4*)&vg[j];
            }
        }
        __syncthreads();

        // S micro-tile: s[i][j] = (Q/8)[r0+i] . K[c0+j]
        float s[8][4];
#pragma unroll
        for (int i = 0; i < 8; i++)
#pragma unroll
            for (int j = 0; j < 4; j++) s[i][j] = 0.0f;
#pragma unroll 8
        for (int d = 0; d < 64; d++) {
            float a[8], bb[4];
            *(float4*)&a[0]  = *(const float4*)&Qt[d * 64 + r0];
            *(float4*)&a[4]  = *(const float4*)&Qt[d * 64 + r0 + 4];
            *(float4*)&bb[0] = *(const float4*)&KP[d * 64 + c0];
#pragma unroll
            for (int i = 0; i < 8; i++)
#pragma unroll
                for (int j = 0; j < 4; j++)
                    s[i][j] += a[i] * bb[j];
        }

        // Online softmax: each row owned by 16 consecutive lanes (xor 8..1)
#pragma unroll
        for (int i = 0; i < 8; i++) {
            float tmax = -1e30f;
#pragma unroll
            for (int j = 0; j < 4; j++) tmax = fmaxf(tmax, s[i][j]);
#pragma unroll
            for (int off = 8; off >= 1; off >>= 1)
                tmax = fmaxf(tmax, __shfl_xor_sync(0xffffffffu, tmax, off));
            float nm = fmaxf(m[i], tmax);
            float corr = __expf(m[i] - nm);
            float ps = 0.0f;
#pragma unroll
            for (int j = 0; j < 4; j++) { s[i][j] = __expf(s[i][j] - nm); ps += s[i][j]; }
#pragma unroll
            for (int off = 8; off >= 1; off >>= 1)
                ps += __shfl_xor_sync(0xffffffffu, ps, off);
            l[i] = l[i] * corr + ps;
            m[i] = nm;
#pragma unroll
            for (int j = 0; j < 4; j++) acc[i][j] *= corr;
        }

        __syncthreads();   // all scores read from KP before overwrite with P
        // Write P into KP, layout [qrow][key]: store float4 at [r0+i][c0]
#pragma unroll
        for (int i = 0; i < 8; i++)
            *(float4*)&KP[(r0 + i) * 64 + c0] = *(float4*)&s[i][0];
        __syncthreads();

        // PV: acc[i][t] += P[r0+i][j] * V[j][c0+t], j-chunks of 4
#pragma unroll 4
        for (int j0 = 0; j0 < 64; j0 += 4) {
            float4 vv0 = *(const float4*)&Vs[(j0 + 0) * 64 + c0];
            float4 vv1 = *(const float4*)&Vs[(j0 + 1) * 64 + c0];
            float4 vv2 = *(const float4*)&Vs[(j0 + 2) * 64 + c0];
            float4 vv3 = *(const float4*)&Vs[(j0 + 3) * 64 + c0];
#pragma unroll
            for (int i = 0; i < 8; i++) {
                float4 p4 = *(const float4*)&KP[(r0 + i) * 64 + j0];  // broadcast
                acc[i][0] += p4.x * vv0.x + p4.y * vv1.x + p4.z * vv2.x + p4.w * vv3.x;
                acc[i][1] += p4.x * vv0.y + p4.y * vv1.y + p4.z * vv2.y + p4.w * vv3.y;
                acc[i][2] += p4.x * vv0.z + p4.y * vv1.z + p4.z * vv2.z + p4.w * vv3.z;
                acc[i][3] += p4.x * vv0.w + p4.y * vv1.w + p4.z * vv2.w + p4.w * vv3.w;
            }
        }
    }

    // Normalize and store
#pragma unroll
    for (int i = 0; i < 8; i++) {
        float inv = 1.0f / l[i];
        float4 o;
        o.x = acc[i][0] * inv;
        o.y = acc[i][1] * inv;
        o.z = acc[i][2] * inv;
        o.w = acc[i][3] * inv;
        *(float4*)&O[((size_t)(b * SS + q0 + r0 + i)) * DD + h * DKH + c0] = o;
    }
}

// ---------------------------------------------------------------------------
extern "C" void kernel_launch(void* const* d_in, const int* in_sizes, int n_in,
                              void* d_out, int out_size)
{
    const float* q  = (const float*)d_in[0];
    const float* k  = (const float*)d_in[1];
    const float* v  = (const float*)d_in[2];
    const float* Wq = (const float*)d_in[3];
    const float* bq = (const float*)d_in[4];
    const float* Wk = (const float*)d_in[5];
    const float* bk = (const float*)d_in[6];
    const float* Wv = (const float*)d_in[7];
    const float* bv = (const float*)d_in[8];
    const float* Wo = (const float*)d_in[9];
    const float* bo = (const float*)d_in[10];
    float* out = (float*)d_out;

    float*  gq; cudaGetSymbolAddress((void**)&gq, g_q);
    float*  gk; cudaGetSymbolAddress((void**)&gk, g_k);
    float*  gv; cudaGetSymbolAddress((void**)&gv, g_v);
    float*  ga; cudaGetSymbolAddress((void**)&ga, g_attn);
    float2* gr; cudaGetSymbolAddress((void**)&gr, g_rope);

    // 0) RoPE cos/sin table
    rope_table_kernel<<<1024 * 32 / 256, 256>>>(gr);

    // 1) Fused QKV projections (+RoPE in Q/K epilogues)
    dim3 ggrid(1024 / 128, MT / 128, 3);
    qkv_gemm_kernel<<<ggrid, 256>>>(q, k, v, Wq, bq, Wk, bk, Wv, bv, gr);

    // 2) Attention (static 48KB smem, 128 threads)
    dim3 agrid(SS / 64, NH, NB);
    attn_kernel<<<agrid, 128>>>(gq, gk, gv, ga);

    // 3) Output projection
    dim3 ogrid(1024 / 128, MT / 128, 1);
    out_gemm_kernel<<<ogrid, 256>>>(Wo, bo, out);
}

// round 13
// speedup vs baseline: 1.4891x; 1.3486x over previous
#include <cuda_runtime.h>
#include <cuda_bf16.h>
#include <stdint.h>
#include <math.h>

#define NB 4
#define SS 1024
#define DD 1024
#define NH 16
#define MT (NB*SS)   // 4096 rows

// ---------------------------------------------------------------------------
// Scratch (__device__ globals; no allocation allowed)
// ---------------------------------------------------------------------------
__device__ float g_q[MT*DD];
__device__ float g_k[MT*DD];
__device__ float g_v[MT*DD];
__device__ float g_attn[MT*DD];
__device__ float2 g_rope[1024*32];                 // [pos][freq] -> (cos,sin)
__device__ __nv_bfloat16 g_ah[3][MT*DD];           // activation hi (q,k,v; slot 0 reused for attn-out)
__device__ __nv_bfloat16 g_al[3][MT*DD];           // activation lo
__device__ __nv_bfloat16 g_wh[4][DD*DD];           // weight hi, TRANSPOSED [n][k]
__device__ __nv_bfloat16 g_wl[4][DD*DD];           // weight lo, TRANSPOSED [n][k]

// ---------------------------------------------------------------------------
// cp.async helpers
// ---------------------------------------------------------------------------
__device__ __forceinline__ void cp16s(uint32_t s, const void* g) {
    asm volatile("cp.async.ca.shared.global [%0], [%1], 16;\n" :: "r"(s), "l"(g));
}
__device__ __forceinline__ void cp_commit() { asm volatile("cp.async.commit_group;\n"); }
__device__ __forceinline__ void cp_wait1()  { asm volatile("cp.async.wait_group 1;\n"); }
__device__ __forceinline__ void cp_wait0()  { asm volatile("cp.async.wait_group 0;\n"); }

__device__ __forceinline__ uint32_t smem_u32(const void* p) {
    uint32_t a;
    asm("{ .reg .u64 t; cvta.to.shared.u64 t, %1; cvt.u32.u64 %0, t; }" : "=r"(a) : "l"(p));
    return a;
}

// Warp MMA: D(m16n8) += A(m16k16,row) * B(k16n8,col)  bf16 in, f32 accum
__device__ __forceinline__ void mma16816(float* c, const uint32_t* a, const uint32_t* b) {
    asm volatile("mma.sync.aligned.m16n8k16.row.col.f32.bf16.bf16.f32 "
        "{%0,%1,%2,%3}, {%4,%5,%6,%7}, {%8,%9}, {%0,%1,%2,%3};"
        : "+f"(c[0]), "+f"(c[1]), "+f"(c[2]), "+f"(c[3])
        : "r"(a[0]), "r"(a[1]), "r"(a[2]), "r"(a[3]), "r"(b[0]), "r"(b[1]));
}

// ---------------------------------------------------------------------------
// RoPE table (reference quirk: pos = (s*16+h) & 1023 applied at use site)
// ---------------------------------------------------------------------------
__global__ __launch_bounds__(256) void rope_table_kernel(float2* __restrict__ tab)
{
    int idx = blockIdx.x * 256 + threadIdx.x;   // 32768
    int i = idx & 31;
    int pos = idx >> 5;
    const double LOG1E4 = 9.210340371976184;
    double inv = exp(-((double)i / 32.0) * LOG1E4);
    double ang = (double)pos * inv;
    tab[idx] = make_float2((float)cos(ang), (float)sin(ang));
}

// ---------------------------------------------------------------------------
// Convert activations: fp32 -> bf16 hi + bf16 lo
// ---------------------------------------------------------------------------
__global__ __launch_bounds__(256) void conva_kernel(
    const float* __restrict__ src, __nv_bfloat16* __restrict__ hi, __nv_bfloat16* __restrict__ lo)
{
    int i = (blockIdx.x * 256 + threadIdx.x) * 4;
    float4 a = *(const float4*)&src[i];
    __nv_bfloat16 h0 = __float2bfloat16(a.x), h1 = __float2bfloat16(a.y);
    __nv_bfloat16 h2 = __float2bfloat16(a.z), h3 = __float2bfloat16(a.w);
    __nv_bfloat16 l0 = __float2bfloat16(a.x - __bfloat162float(h0));
    __nv_bfloat16 l1 = __float2bfloat16(a.y - __bfloat162float(h1));
    __nv_bfloat16 l2 = __float2bfloat16(a.z - __bfloat162float(h2));
    __nv_bfloat16 l3 = __float2bfloat16(a.w - __bfloat162float(h3));
    __nv_bfloat162* H = (__nv_bfloat162*)&hi[i];
    __nv_bfloat162* L = (__nv_bfloat162*)&lo[i];
    H[0] = __halves2bfloat162(h0, h1); H[1] = __halves2bfloat162(h2, h3);
    L[0] = __halves2bfloat162(l0, l1); L[1] = __halves2bfloat162(l2, l3);
}

// ---------------------------------------------------------------------------
// Convert + transpose weights: W[k][n] fp32 -> Wt_hi/lo[n][k] bf16
// grid (32, 32, 4), block 256 (32x8)
// ---------------------------------------------------------------------------
__global__ __launch_bounds__(256) void convw_kernel(
    const float* __restrict__ Wq, const float* __restrict__ Wk,
    const float* __restrict__ Wv, const float* __restrict__ Wo,
    __nv_bfloat16* __restrict__ th, __nv_bfloat16* __restrict__ tl)
{
    __shared__ float t[32][33];
    const float* W = (blockIdx.z == 0) ? Wq : (blockIdx.z == 1) ? Wk : (blockIdx.z == 2) ? Wv : Wo;
    __nv_bfloat16* oh = th + (size_t)blockIdx.z * DD * DD;
    __nv_bfloat16* ol = tl + (size_t)blockIdx.z * DD * DD;
    int n0 = blockIdx.x * 32, k0 = blockIdx.y * 32;
    int tx = threadIdx.x & 31, ty = threadIdx.x >> 5;
#pragma unroll
    for (int r = 0; r < 32; r += 8)
        t[ty + r][tx] = W[(size_t)(k0 + ty + r) * DD + n0 + tx];
    __syncthreads();
#pragma unroll
    for (int r = 0; r < 32; r += 8) {
        float v = t[tx][ty + r];                       // = W[k0+tx][n0+ty+r]
        __nv_bfloat16 h = __float2bfloat16(v);
        __nv_bfloat16 l = __float2bfloat16(v - __bfloat162float(h));
        size_t o = (size_t)(n0 + ty + r) * DD + k0 + tx;
        oh[o] = h; ol[o] = l;
    }
}

// ---------------------------------------------------------------------------
// Warp-MMA bf16-split GEMM: C[4096,1024] = A @ W + bias (optional fused RoPE)
// CTA: 128 (M) x 64 (N = one head). 256 threads = 8 warps (4 M x 2 N),
// warp tile 32x32 = 2x4 m16n8 fragments. 3 split terms: AhBh + AhBl + AlBh.
// K=1024, BK=32, 2-stage cp.async. Smem rows padded to 40 bf16 (20 words):
// fragment reads are bank-conflict-free (g*20+tig distinct mod 32).
// Dyn smem: 2 stages x [Ah 10240 | Al 10240 | Bh 5120 | Bl 5120] = 61440 B.
// ---------------------------------------------------------------------------
#define SAP 10240
#define SBP 5120
#define STG (2*SAP + 2*SBP)     // 30720 per stage
#define GSMEM (2*STG)           // 61440

__global__ void __launch_bounds__(256) mma_gemm_kernel(
    const __nv_bfloat16* __restrict__ Ah, const __nv_bfloat16* __restrict__ Al,
    const __nv_bfloat16* __restrict__ Bh, const __nv_bfloat16* __restrict__ Bl,
    const float* __restrict__ bias, float* __restrict__ C,
    const float2* __restrict__ rope, int do_rope)
{
    extern __shared__ __align__(16) char dsm[];
    const uint32_t sb = smem_u32(dsm);
    const int tid  = threadIdx.x;
    const int lane = tid & 31;
    const int warp = tid >> 5;
    const int wm = warp >> 1, wn = warp & 1;        // 4 M x 2 N warp grid (FIX)
    const int g = lane >> 2, tig = lane & 3;
    const int bm = blockIdx.y * 128;
    const int bn = blockIdx.x * 64;                 // head * 64

    // ---- copy indices ----
    const int ar  = tid >> 1;          // A row 0..127
    const int ah2 = (tid & 1) * 16;    // col half (bf16 units): 0 or 16
    const int br  = tid >> 2;          // B row 0..63
    const int bq4 = (tid & 3) * 8;     // col quarter: 0,8,16,24

#define LOAD_STAGE(c, buf) do {                                                   \
        uint32_t base = sb + (buf) * STG;                                         \
        int k0 = (c) * 32;                                                        \
        const __nv_bfloat16* pah = Ah + (size_t)(bm + ar) * 1024 + k0 + ah2;      \
        const __nv_bfloat16* pal = Al + (size_t)(bm + ar) * 1024 + k0 + ah2;      \
        uint32_t ao = base + (uint32_t)ar * 80u + (uint32_t)(ah2 * 2);            \
        cp16s(ao,              pah);                                              \
        cp16s(ao + 16,         pah + 8);                                          \
        cp16s(ao + SAP,        pal);                                              \
        cp16s(ao + SAP + 16,   pal + 8);                                          \
        const __nv_bfloat16* pbh = Bh + (size_t)(bn + br) * 1024 + k0 + bq4;      \
        const __nv_bfloat16* pbl = Bl + (size_t)(bn + br) * 1024 + k0 + bq4;      \
        uint32_t bo = base + 2*SAP + (uint32_t)br * 80u + (uint32_t)(bq4 * 2);    \
        cp16s(bo,        pbh);                                                    \
        cp16s(bo + SBP,  pbl);                                                    \
    } while (0)

    float c_[2][4][4];
#pragma unroll
    for (int mt = 0; mt < 2; mt++)
#pragma unroll
        for (int nt = 0; nt < 4; nt++)
#pragma unroll
            for (int r = 0; r < 4; r++) c_[mt][nt][r] = 0.0f;

    LOAD_STAGE(0, 0);
    cp_commit();

    for (int c = 0; c < 32; c++) {
        if (c + 1 < 32) { LOAD_STAGE(c + 1, (c + 1) & 1); cp_commit(); cp_wait1(); }
        else            { cp_wait0(); }
        __syncthreads();

        const uint32_t* wAh = (const uint32_t*)(dsm + (c & 1) * STG);
        const uint32_t* wAl = (const uint32_t*)(dsm + (c & 1) * STG + SAP);
        const uint32_t* wBh = (const uint32_t*)(dsm + (c & 1) * STG + 2 * SAP);
        const uint32_t* wBl = (const uint32_t*)(dsm + (c & 1) * STG + 2 * SAP + SBP);

#pragma unroll
        for (int kk = 0; kk < 2; kk++) {
            const int ko = kk * 8;     // word offset within 20-word row
            uint32_t fah[2][4], fal[2][4];
#pragma unroll
            for (int mt = 0; mt < 2; mt++) {
                int r0 = (wm * 32 + mt * 16 + g) * 20 + ko + tig;
                int r1 = (wm * 32 + mt * 16 + g + 8) * 20 + ko + tig;
                fah[mt][0] = wAh[r0];     fah[mt][1] = wAh[r1];
                fah[mt][2] = wAh[r0 + 4]; fah[mt][3] = wAh[r1 + 4];
                fal[mt][0] = wAl[r0];     fal[mt][1] = wAl[r1];
                fal[mt][2] = wAl[r0 + 4]; fal[mt][3] = wAl[r1 + 4];
            }
            uint32_t fbh[4][2], fbl[4][2];
#pragma unroll
            for (int nt = 0; nt < 4; nt++) {
                int n = (wn * 32 + nt * 8 + g) * 20 + ko + tig;
                fbh[nt][0] = wBh[n]; fbh[nt][1] = wBh[n + 4];
                fbl[nt][0] = wBl[n]; fbl[nt][1] = wBl[n + 4];
            }
#pragma unroll
            for (int mt = 0; mt < 2; mt++)
#pragma unroll
                for (int nt = 0; nt < 4; nt++) {
                    mma16816(c_[mt][nt], fah[mt], fbh[nt]);
                    mma16816(c_[mt][nt], fah[mt], fbl[nt]);
                    mma16816(c_[mt][nt], fal[mt], fbh[nt]);
                }
        }
        __syncthreads();
    }
#undef LOAD_STAGE

    // ---- epilogue: bias + optional RoPE, direct register stores ----
    const int head = blockIdx.x;
#pragma unroll
    for (int mt = 0; mt < 2; mt++) {
        int row0 = bm + wm * 32 + mt * 16 + g;
        int row1 = row0 + 8;
        int pos0 = 0, pos1 = 0;
        if (do_rope) {
            pos0 = (((row0 & 1023) * 16 + head) & 1023);
            pos1 = (((row1 & 1023) * 16 + head) & 1023);
        }
#pragma unroll
        for (int nt = 0; nt < 4; nt++) {
            int col = bn + wn * 32 + nt * 8 + tig * 2;
            float b0 = bias[col], b1 = bias[col + 1];
            float x0 = c_[mt][nt][0] + b0, x1 = c_[mt][nt][1] + b1;
            float y0 = c_[mt][nt][2] + b0, y1 = c_[mt][nt][3] + b1;
            if (do_rope) {
                int i = wn * 16 + nt * 4 + tig;     // (col & 63) >> 1
                float2 cs0 = rope[pos0 * 32 + i];
                float2 cs1 = rope[pos1 * 32 + i];
                float t0 = x0 * cs0.x - x1 * cs0.y;
                x1 = x0 * cs0.y + x1 * cs0.x; x0 = t0;
                float t1 = y0 * cs1.x - y1 * cs1.y;
                y1 = y0 * cs1.y + y1 * cs1.x; y0 = t1;
            }
            *(float2*)&C[(size_t)row0 * 1024 + col] = make_float2(x0, x1);
            *(float2*)&C[(size_t)row1 * 1024 + col] = make_float2(y0, y1);
        }
    }
}

// ---------------------------------------------------------------------------
// Flash attention (unchanged, fp32): grid (S/64, H, B), 128 thr, 48KB static.
// ---------------------------------------------------------------------------
__global__ __launch_bounds__(128) void attn_kernel(
    const float* __restrict__ Q, const float* __restrict__ K,
    const float* __restrict__ V, float* __restrict__ O)
{
    __shared__ float Qt[64 * 64];
    __shared__ float KP[64 * 64];
    __shared__ float Vs[64 * 64];

    const int tid = threadIdx.x;
    const int h = blockIdx.y, b = blockIdx.z;
    const int q0 = blockIdx.x * 64;
    const int rg = tid >> 4, cg = tid & 15;
    const int r0 = rg * 8, c0 = cg * 4;

    {
        const int lr = tid >> 1;
        const int dof = (tid & 1) * 32;
        const float* qg = Q + ((size_t)(b * SS + q0 + lr)) * DD + h * 64 + dof;
#pragma unroll
        for (int j = 0; j < 32; j += 4) {
            float4 v4 = *(const float4*)&qg[j];
            Qt[(dof + j + 0) * 64 + lr] = v4.x * 0.125f;
            Qt[(dof + j + 1) * 64 + lr] = v4.y * 0.125f;
            Qt[(dof + j + 2) * 64 + lr] = v4.z * 0.125f;
            Qt[(dof + j + 3) * 64 + lr] = v4.w * 0.125f;
        }
    }

    float m[8], l[8], acc[8][4];
#pragma unroll
    for (int i = 0; i < 8; i++) {
        m[i] = -1e30f; l[i] = 0.0f;
#pragma unroll
        for (int j = 0; j < 4; j++) acc[i][j] = 0.0f;
    }

    const int kr = tid >> 1;
    const int kd = (tid & 1) * 32;

    for (int kt = 0; kt < 16; kt++) {
        __syncthreads();
        {
            const float* kg = K + ((size_t)(b * SS + kt * 64 + kr)) * DD + h * 64 + kd;
            const float* vg = V + ((size_t)(b * SS + kt * 64 + kr)) * DD + h * 64 + kd;
#pragma unroll
            for (int j = 0; j < 32; j += 4) {
                float4 kv = *(const float4*)&kg[j];
                KP[(kd + j + 0) * 64 + kr] = kv.x;
                KP[(kd + j + 1) * 64 + kr] = kv.y;
                KP[(kd + j + 2) * 64 + kr] = kv.z;
                KP[(kd + j + 3) * 64 + kr] = kv.w;
                *(float4*)&Vs[kr * 64 + kd + j] = *(const float4*)&vg[j];
            }
        }
        __syncthreads();

        float s[8][4];
#pragma unroll
        for (int i = 0; i < 8; i++)
#pragma unroll
            for (int j = 0; j < 4; j++) s[i][j] = 0.0f;
#pragma unroll 8
        for (int d = 0; d < 64; d++) {
            float a[8], bb[4];
            *(float4*)&a[0]  = *(const float4*)&Qt[d * 64 + r0];
            *(float4*)&a[4]  = *(const float4*)&Qt[d * 64 + r0 + 4];
            *(float4*)&bb[0] = *(const float4*)&KP[d * 64 + c0];
#pragma unroll
            for (int i = 0; i < 8; i++)
#pragma unroll
                for (int j = 0; j < 4; j++)
                    s[i][j] += a[i] * bb[j];
        }

#pragma unroll
        for (int i = 0; i < 8; i++) {
            float tmax = -1e30f;
#pragma unroll
            for (int j = 0; j < 4; j++) tmax = fmaxf(tmax, s[i][j]);
#pragma unroll
            for (int off = 8; off >= 1; off >>= 1)
                tmax = fmaxf(tmax, __shfl_xor_sync(0xffffffffu, tmax, off));
            float nm = fmaxf(m[i], tmax);
            float corr = __expf(m[i] - nm);
            float ps = 0.0f;
#pragma unroll
            for (int j = 0; j < 4; j++) { s[i][j] = __expf(s[i][j] - nm); ps += s[i][j]; }
#pragma unroll
            for (int off = 8; off >= 1; off >>= 1)
                ps += __shfl_xor_sync(0xffffffffu, ps, off);
            l[i] = l[i] * corr + ps;
            m[i] = nm;
#pragma unroll
            for (int j = 0; j < 4; j++) acc[i][j] *= corr;
        }

        __syncthreads();
#pragma unroll
        for (int i = 0; i < 8; i++)
            *(float4*)&KP[(r0 + i) * 64 + c0] = *(float4*)&s[i][0];
        __syncthreads();

#pragma unroll 4
        for (int j0 = 0; j0 < 64; j0 += 4) {
            float4 vv0 = *(const float4*)&Vs[(j0 + 0) * 64 + c0];
            float4 vv1 = *(const float4*)&Vs[(j0 + 1) * 64 + c0];
            float4 vv2 = *(const float4*)&Vs[(j0 + 2) * 64 + c0];
            float4 vv3 = *(const float4*)&Vs[(j0 + 3) * 64 + c0];
#pragma unroll
            for (int i = 0; i < 8; i++) {
                float4 p4 = *(const float4*)&KP[(r0 + i) * 64 + j0];
                acc[i][0] += p4.x * vv0.x + p4.y * vv1.x + p4.z * vv2.x + p4.w * vv3.x;
                acc[i][1] += p4.x * vv0.y + p4.y * vv1.y + p4.z * vv2.y + p4.w * vv3.y;
                acc[i][2] += p4.x * vv0.z + p4.y * vv1.z + p4.z * vv2.z + p4.w * vv3.z;
                acc[i][3] += p4.x * vv0.w + p4.y * vv1.w + p4.z * vv2.w + p4.w * vv3.w;
            }
        }
    }

#pragma unroll
    for (int i = 0; i < 8; i++) {
        float inv = 1.0f / l[i];
        float4 o;
        o.x = acc[i][0] * inv;
        o.y = acc[i][1] * inv;
        o.z = acc[i][2] * inv;
        o.w = acc[i][3] * inv;
        *(float4*)&O[((size_t)(b * SS + q0 + r0 + i)) * DD + h * 64 + c0] = o;
    }
}

// ---------------------------------------------------------------------------
extern "C" void kernel_launch(void* const* d_in, const int* in_sizes, int n_in,
                              void* d_out, int out_size)
{
    const float* q  = (const float*)d_in[0];
    const float* k  = (const float*)d_in[1];
    const float* v  = (const float*)d_in[2];
    const float* Wq = (const float*)d_in[3];
    const float* bq = (const float*)d_in[4];
    const float* Wk = (const float*)d_in[5];
    const float* bk = (const float*)d_in[6];
    const float* Wv = (const float*)d_in[7];
    const float* bv = (const float*)d_in[8];
    const float* Wo = (const float*)d_in[9];
    const float* bo = (const float*)d_in[10];
    float* out = (float*)d_out;

    float*  gq; cudaGetSymbolAddress((void**)&gq, g_q);
    float*  gk; cudaGetSymbolAddress((void**)&gk, g_k);
    float*  gv; cudaGetSymbolAddress((void**)&gv, g_v);
    float*  ga; cudaGetSymbolAddress((void**)&ga, g_attn);
    float2* gr; cudaGetSymbolAddress((void**)&gr, g_rope);
    __nv_bfloat16* ah; cudaGetSymbolAddress((void**)&ah, g_ah);
    __nv_bfloat16* al; cudaGetSymbolAddress((void**)&al, g_al);
    __nv_bfloat16* wh; cudaGetSymbolAddress((void**)&wh, g_wh);
    __nv_bfloat16* wl; cudaGetSymbolAddress((void**)&wl, g_wl);

    cudaFuncSetAttribute(mma_gemm_kernel, cudaFuncAttributeMaxDynamicSharedMemorySize, GSMEM);

    const size_t AD = (size_t)MT * DD;   // 4M elems
    const size_t WD = (size_t)DD * DD;   // 1M elems

    // 0) RoPE table + weight convert/transpose
    rope_table_kernel<<<1024 * 32 / 256, 256>>>(gr);
    convw_kernel<<<dim3(32, 32, 4), 256>>>(Wq, Wk, Wv, Wo, wh, wl);

    // 1) Activation converts (q,k,v)
    conva_kernel<<<AD / 1024, 256>>>(q, ah + 0 * AD, al + 0 * AD);
    conva_kernel<<<AD / 1024, 256>>>(k, ah + 1 * AD, al + 1 * AD);
    conva_kernel<<<AD / 1024, 256>>>(v, ah + 2 * AD, al + 2 * AD);

    // 2) Projection GEMMs (warp-MMA bf16 split, RoPE fused for Q/K)
    dim3 ggrid(16, 32);
    mma_gemm_kernel<<<ggrid, 256, GSMEM>>>(ah + 0 * AD, al + 0 * AD, wh + 0 * WD, wl + 0 * WD, bq, gq, gr, 1);
    mma_gemm_kernel<<<ggrid, 256, GSMEM>>>(ah + 1 * AD, al + 1 * AD, wh + 1 * WD, wl + 1 * WD, bk, gk, gr, 1);
    mma_gemm_kernel<<<ggrid, 256, GSMEM>>>(ah + 2 * AD, al + 2 * AD, wh + 2 * WD, wl + 2 * WD, bv, gv, gr, 0);

    // 3) Attention (fp32)
    dim3 agrid(SS / 64, NH, NB);
    attn_kernel<<<agrid, 128>>>(gq, gk, gv, ga);

    // 4) Output projection (convert attn-out, then GEMM)
    conva_kernel<<<AD / 1024, 256>>>(ga, ah + 0 * AD, al + 0 * AD);
    mma_gemm_kernel<<<ggrid, 256, GSMEM>>>(ah + 0 * AD, al + 0 * AD, wh + 3 * WD, wl + 3 * WD, bo, out, gr, 0);
}

// round 14
// speedup vs baseline: 1.9678x; 1.3215x over previous
#include <cuda_runtime.h>
#include <cuda_bf16.h>
#include <stdint.h>
#include <math.h>

#define NB 4
#define SS 1024
#define DD 1024
#define NH 16
#define MT (NB*SS)   // 4096 rows

// ---------------------------------------------------------------------------
// Scratch (__device__ globals; no allocation allowed)
// ---------------------------------------------------------------------------
__device__ float2 g_rope[1024*32];                 // [pos][freq] -> (cos,sin)
__device__ __nv_bfloat16 g_ah[3][MT*DD];           // input splits (q,k,v); slot0 reused for attn-out
__device__ __nv_bfloat16 g_al[3][MT*DD];
__device__ __nv_bfloat16 g_wh[4][DD*DD];           // weight hi, TRANSPOSED [n][k]
__device__ __nv_bfloat16 g_wl[4][DD*DD];           // weight lo, TRANSPOSED [n][k]
__device__ __nv_bfloat16 g_qh[MT*DD], g_ql[MT*DD]; // projected Q (rope, x0.125) hi/lo
__device__ __nv_bfloat16 g_kh[MT*DD], g_kl[MT*DD]; // projected K (rope) hi/lo
__device__ __nv_bfloat16 g_vh[MT*DD], g_vl[MT*DD]; // projected V hi/lo

// ---------------------------------------------------------------------------
// helpers
// ---------------------------------------------------------------------------
__device__ __forceinline__ void cp16s(uint32_t s, const void* g) {
    asm volatile("cp.async.ca.shared.global [%0], [%1], 16;\n" :: "r"(s), "l"(g));
}
__device__ __forceinline__ void cp_commit() { asm volatile("cp.async.commit_group;\n"); }
__device__ __forceinline__ void cp_wait1()  { asm volatile("cp.async.wait_group 1;\n"); }
__device__ __forceinline__ void cp_wait0()  { asm volatile("cp.async.wait_group 0;\n"); }
__device__ __forceinline__ uint32_t smem_u32(const void* p) {
    uint32_t a;
    asm("{ .reg .u64 t; cvta.to.shared.u64 t, %1; cvt.u32.u64 %0, t; }" : "=r"(a) : "l"(p));
    return a;
}
// Warp MMA: D(m16n8) += A(m16k16,row) * B(k16n8,col)  bf16 in, f32 accum
__device__ __forceinline__ void mma16816(float* c, const uint32_t* a, const uint32_t* b) {
    asm volatile("mma.sync.aligned.m16n8k16.row.col.f32.bf16.bf16.f32 "
        "{%0,%1,%2,%3}, {%4,%5,%6,%7}, {%8,%9}, {%0,%1,%2,%3};"
        : "+f"(c[0]), "+f"(c[1]), "+f"(c[2]), "+f"(c[3])
        : "r"(a[0]), "r"(a[1]), "r"(a[2]), "r"(a[3]), "r"(b[0]), "r"(b[1]));
}
// split (a,b) fp32 -> packed bf16x2 hi word + lo word
__device__ __forceinline__ void split2(float a, float b, uint32_t& hi, uint32_t& lo) {
    __nv_bfloat16 ha = __float2bfloat16(a), hb = __float2bfloat16(b);
    __nv_bfloat16 la = __float2bfloat16(a - __bfloat162float(ha));
    __nv_bfloat16 lb = __float2bfloat16(b - __bfloat162float(hb));
    __nv_bfloat162 H = __halves2bfloat162(ha, hb), L = __halves2bfloat162(la, lb);
    hi = *(uint32_t*)&H; lo = *(uint32_t*)&L;
}

// ---------------------------------------------------------------------------
// RoPE table (reference quirk: pos = (s*16+h) & 1023 applied at use site)
// ---------------------------------------------------------------------------
__global__ __launch_bounds__(256) void rope_table_kernel(float2* __restrict__ tab)
{
    int idx = blockIdx.x * 256 + threadIdx.x;   // 32768
    int i = idx & 31;
    int pos = idx >> 5;
    const double LOG1E4 = 9.210340371976184;
    double inv = exp(-((double)i / 32.0) * LOG1E4);
    double ang = (double)pos * inv;
    tab[idx] = make_float2((float)cos(ang), (float)sin(ang));
}

// ---------------------------------------------------------------------------
// Convert activations: fp32 -> bf16 hi + bf16 lo
// ---------------------------------------------------------------------------
__global__ __launch_bounds__(256) void conva_kernel(
    const float* __restrict__ src, __nv_bfloat16* __restrict__ hi, __nv_bfloat16* __restrict__ lo)
{
    int i = (blockIdx.x * 256 + threadIdx.x) * 4;
    float4 a = *(const float4*)&src[i];
    uint32_t h0, l0, h1, l1;
    split2(a.x, a.y, h0, l0);
    split2(a.z, a.w, h1, l1);
    uint32_t* H = (uint32_t*)&hi[i];
    uint32_t* L = (uint32_t*)&lo[i];
    H[0] = h0; H[1] = h1; L[0] = l0; L[1] = l1;
}

// ---------------------------------------------------------------------------
// Convert + transpose weights: W[k][n] fp32 -> Wt_hi/lo[n][k] bf16
// ---------------------------------------------------------------------------
__global__ __launch_bounds__(256) void convw_kernel(
    const float* __restrict__ Wq, const float* __restrict__ Wk,
    const float* __restrict__ Wv, const float* __restrict__ Wo,
    __nv_bfloat16* __restrict__ th, __nv_bfloat16* __restrict__ tl)
{
    __shared__ float t[32][33];
    const float* W = (blockIdx.z == 0) ? Wq : (blockIdx.z == 1) ? Wk : (blockIdx.z == 2) ? Wv : Wo;
    __nv_bfloat16* oh = th + (size_t)blockIdx.z * DD * DD;
    __nv_bfloat16* ol = tl + (size_t)blockIdx.z * DD * DD;
    int n0 = blockIdx.x * 32, k0 = blockIdx.y * 32;
    int tx = threadIdx.x & 31, ty = threadIdx.x >> 5;
#pragma unroll
    for (int r = 0; r < 32; r += 8)
        t[ty + r][tx] = W[(size_t)(k0 + ty + r) * DD + n0 + tx];
    __syncthreads();
#pragma unroll
    for (int r = 0; r < 32; r += 8) {
        float v = t[tx][ty + r];
        __nv_bfloat16 h = __float2bfloat16(v);
        __nv_bfloat16 l = __float2bfloat16(v - __bfloat162float(h));
        size_t o = (size_t)(n0 + ty + r) * DD + k0 + tx;
        oh[o] = h; ol[o] = l;
    }
}

// ---------------------------------------------------------------------------
// Warp-MMA bf16-split GEMM. CTA 128(M) x 64(N=head). 8 warps (4Mx2N).
// Epilogue: bias + optional RoPE + scale; writes fp32 (Cf) OR split bf16 (Ch/Cl).
// ---------------------------------------------------------------------------
#define SAP 10240
#define SBP 5120
#define STG (2*SAP + 2*SBP)
#define GSMEM (2*STG)           // 61440

__global__ void __launch_bounds__(256) mma_gemm_kernel(
    const __nv_bfloat16* __restrict__ Ah, const __nv_bfloat16* __restrict__ Al,
    const __nv_bfloat16* __restrict__ Bh, const __nv_bfloat16* __restrict__ Bl,
    const float* __restrict__ bias,
    float* __restrict__ Cf, __nv_bfloat16* __restrict__ Ch, __nv_bfloat16* __restrict__ Cl,
    const float2* __restrict__ rope, int do_rope, float scale)
{
    extern __shared__ __align__(16) char dsm[];
    const uint32_t sb = smem_u32(dsm);
    const int tid  = threadIdx.x;
    const int lane = tid & 31;
    const int warp = tid >> 5;
    const int wm = warp >> 1, wn = warp & 1;        // 4M x 2N
    const int g = lane >> 2, tig = lane & 3;
    const int bm = blockIdx.y * 128;
    const int bn = blockIdx.x * 64;

    const int ar  = tid >> 1;
    const int ah2 = (tid & 1) * 16;
    const int br  = tid >> 2;
    const int bq4 = (tid & 3) * 8;

#define LOAD_STAGE(c, buf) do {                                                   \
        uint32_t base = sb + (buf) * STG;                                         \
        int k0 = (c) * 32;                                                        \
        const __nv_bfloat16* pah = Ah + (size_t)(bm + ar) * 1024 + k0 + ah2;      \
        const __nv_bfloat16* pal = Al + (size_t)(bm + ar) * 1024 + k0 + ah2;      \
        uint32_t ao = base + (uint32_t)ar * 80u + (uint32_t)(ah2 * 2);            \
        cp16s(ao,              pah);                                              \
        cp16s(ao + 16,         pah + 8);                                          \
        cp16s(ao + SAP,        pal);                                              \
        cp16s(ao + SAP + 16,   pal + 8);                                          \
        const __nv_bfloat16* pbh = Bh + (size_t)(bn + br) * 1024 + k0 + bq4;      \
        const __nv_bfloat16* pbl = Bl + (size_t)(bn + br) * 1024 + k0 + bq4;      \
        uint32_t bo = base + 2*SAP + (uint32_t)br * 80u + (uint32_t)(bq4 * 2);    \
        cp16s(bo,        pbh);                                                    \
        cp16s(bo + SBP,  pbl);                                                    \
    } while (0)

    float c_[2][4][4];
#pragma unroll
    for (int mt = 0; mt < 2; mt++)
#pragma unroll
        for (int nt = 0; nt < 4; nt++)
#pragma unroll
            for (int r = 0; r < 4; r++) c_[mt][nt][r] = 0.0f;

    LOAD_STAGE(0, 0);
    cp_commit();

    for (int c = 0; c < 32; c++) {
        if (c + 1 < 32) { LOAD_STAGE(c + 1, (c + 1) & 1); cp_commit(); cp_wait1(); }
        else            { cp_wait0(); }
        __syncthreads();

        const uint32_t* wAh = (const uint32_t*)(dsm + (c & 1) * STG);
        const uint32_t* wAl = (const uint32_t*)(dsm + (c & 1) * STG + SAP);
        const uint32_t* wBh = (const uint32_t*)(dsm + (c & 1) * STG + 2 * SAP);
        const uint32_t* wBl = (const uint32_t*)(dsm + (c & 1) * STG + 2 * SAP + SBP);

#pragma unroll
        for (int kk = 0; kk < 2; kk++) {
            const int ko = kk * 8;
            uint32_t fah[2][4], fal[2][4];
#pragma unroll
            for (int mt = 0; mt < 2; mt++) {
                int r0 = (wm * 32 + mt * 16 + g) * 20 + ko + tig;
                int r1 = (wm * 32 + mt * 16 + g + 8) * 20 + ko + tig;
                fah[mt][0] = wAh[r0];     fah[mt][1] = wAh[r1];
                fah[mt][2] = wAh[r0 + 4]; fah[mt][3] = wAh[r1 + 4];
                fal[mt][0] = wAl[r0];     fal[mt][1] = wAl[r1];
                fal[mt][2] = wAl[r0 + 4]; fal[mt][3] = wAl[r1 + 4];
            }
            uint32_t fbh[4][2], fbl[4][2];
#pragma unroll
            for (int nt = 0; nt < 4; nt++) {
                int n = (wn * 32 + nt * 8 + g) * 20 + ko + tig;
                fbh[nt][0] = wBh[n]; fbh[nt][1] = wBh[n + 4];
                fbl[nt][0] = wBl[n]; fbl[nt][1] = wBl[n + 4];
            }
#pragma unroll
            for (int mt = 0; mt < 2; mt++)
#pragma unroll
                for (int nt = 0; nt < 4; nt++) {
                    mma16816(c_[mt][nt], fah[mt], fbh[nt]);
                    mma16816(c_[mt][nt], fah[mt], fbl[nt]);
                    mma16816(c_[mt][nt], fal[mt], fbh[nt]);
                }
        }
        __syncthreads();
    }
#undef LOAD_STAGE

    const int head = blockIdx.x;
#pragma unroll
    for (int mt = 0; mt < 2; mt++) {
        int row0 = bm + wm * 32 + mt * 16 + g;
        int row1 = row0 + 8;
        int pos0 = 0, pos1 = 0;
        if (do_rope) {
            pos0 = (((row0 & 1023) * 16 + head) & 1023);
            pos1 = (((row1 & 1023) * 16 + head) & 1023);
        }
#pragma unroll
        for (int nt = 0; nt < 4; nt++) {
            int col = bn + wn * 32 + nt * 8 + tig * 2;
            float b0 = bias[col], b1 = bias[col + 1];
            float x0 = c_[mt][nt][0] + b0, x1 = c_[mt][nt][1] + b1;
            float y0 = c_[mt][nt][2] + b0, y1 = c_[mt][nt][3] + b1;
            if (do_rope) {
                int i = wn * 16 + nt * 4 + tig;
                float2 cs0 = rope[pos0 * 32 + i];
                float2 cs1 = rope[pos1 * 32 + i];
                float t0 = x0 * cs0.x - x1 * cs0.y;
                x1 = x0 * cs0.y + x1 * cs0.x; x0 = t0;
                float t1 = y0 * cs1.x - y1 * cs1.y;
                y1 = y0 * cs1.y + y1 * cs1.x; y0 = t1;
            }
            x0 *= scale; x1 *= scale; y0 *= scale; y1 *= scale;
            if (Cf) {
                *(float2*)&Cf[(size_t)row0 * 1024 + col] = make_float2(x0, x1);
                *(float2*)&Cf[(size_t)row1 * 1024 + col] = make_float2(y0, y1);
            } else {
                uint32_t hw, lw;
                split2(x0, x1, hw, lw);
                ((uint32_t*)Ch)[((size_t)row0 * 1024 + col) >> 1] = hw;
                ((uint32_t*)Cl)[((size_t)row0 * 1024 + col) >> 1] = lw;
                split2(y0, y1, hw, lw);
                ((uint32_t*)Ch)[((size_t)row1 * 1024 + col) >> 1] = hw;
                ((uint32_t*)Cl)[((size_t)row1 * 1024 + col) >> 1] = lw;
            }
        }
    }
}

// ---------------------------------------------------------------------------
// MMA flash attention: grid (16 qtiles, 16 h, 4 b), 128 threads (4 warps).
// Tiles 64q x 64k, d=64. S via 3-term bf16-split mma; softmax in registers;
// P split in registers (S C-frag == PV A-frag layout); PV via 3-term mma.
// Smem: 8 tiles of 64 rows x 72 bf16 (stride 36 words, conflict-free frags):
// Qh Ql Kh Kl Vh Vl Th Tl (T = V transposed [d][key]). 73728 B dynamic.
// Output written as bf16 hi/lo split for the out-projection GEMM.
// ---------------------------------------------------------------------------
#define TW 36
#define TB 9216
#define ASMEM (8*TB)   // 73728

__global__ void __launch_bounds__(128) attn_mma_kernel(
    const __nv_bfloat16* __restrict__ Qh, const __nv_bfloat16* __restrict__ Ql,
    const __nv_bfloat16* __restrict__ Kh, const __nv_bfloat16* __restrict__ Kl,
    const __nv_bfloat16* __restrict__ Vh, const __nv_bfloat16* __restrict__ Vl,
    __nv_bfloat16* __restrict__ Oh, __nv_bfloat16* __restrict__ Ol)
{
    extern __shared__ __align__(16) char sm_[];
    const uint32_t sb = smem_u32(sm_);
    const int tid  = threadIdx.x;
    const int lane = tid & 31;
    const int warp = tid >> 5;                 // 0..3: 16 q-rows each
    const int g = lane >> 2, tig = lane & 3;
    const int h = blockIdx.y, b = blockIdx.z;
    const int q0 = blockIdx.x * 64;

    const int lrow = tid >> 1;                 // 0..63
    const int lhalf = (tid & 1) * 32;          // bf16 units

    // ---- load Q tile (hi/lo) once ----
    {
        const __nv_bfloat16* ph = Qh + ((size_t)(b * 1024 + q0 + lrow)) * 1024 + h * 64 + lhalf;
        const __nv_bfloat16* pl = Ql + ((size_t)(b * 1024 + q0 + lrow)) * 1024 + h * 64 + lhalf;
        uint32_t dh = sb + 0 * TB + lrow * 144 + lhalf * 2;
        uint32_t dl = sb + 1 * TB + lrow * 144 + lhalf * 2;
#pragma unroll
        for (int j = 0; j < 4; j++) {
            cp16s(dh + j * 16, ph + j * 8);
            cp16s(dl + j * 16, pl + j * 8);
        }
    }

    const uint32_t* sQh = (const uint32_t*)(sm_ + 0 * TB);
    const uint32_t* sQl = (const uint32_t*)(sm_ + 1 * TB);
    const uint32_t* sKh = (const uint32_t*)(sm_ + 2 * TB);
    const uint32_t* sKl = (const uint32_t*)(sm_ + 3 * TB);
    const uint32_t* sVh32 = (const uint32_t*)(sm_ + 4 * TB);
    const uint32_t* sVl32 = (const uint32_t*)(sm_ + 5 * TB);
    __nv_bfloat16* sTh = (__nv_bfloat16*)(sm_ + 6 * TB);
    __nv_bfloat16* sTl = (__nv_bfloat16*)(sm_ + 7 * TB);
    const uint32_t* sTh32 = (const uint32_t*)(sm_ + 6 * TB);
    const uint32_t* sTl32 = (const uint32_t*)(sm_ + 7 * TB);

    float mA = -1e30f, mB = -1e30f, lA = 0.0f, lB = 0.0f;
    float o[8][4];
#pragma unroll
    for (int j = 0; j < 8; j++)
#pragma unroll
        for (int r = 0; r < 4; r++) o[j][r] = 0.0f;

    for (int kt = 0; kt < 16; kt++) {
        if (kt > 0) __syncthreads();     // prev PV done with sT; prev S done with sK
        // load K,V tiles (hi/lo)
        {
            size_t grow = ((size_t)(b * 1024 + kt * 64 + lrow)) * 1024 + h * 64 + lhalf;
            uint32_t dkh = sb + 2 * TB + lrow * 144 + lhalf * 2;
            uint32_t dkl = sb + 3 * TB + lrow * 144 + lhalf * 2;
            uint32_t dvh = sb + 4 * TB + lrow * 144 + lhalf * 2;
            uint32_t dvl = sb + 5 * TB + lrow * 144 + lhalf * 2;
#pragma unroll
            for (int j = 0; j < 4; j++) {
                cp16s(dkh + j * 16, Kh + grow + j * 8);
                cp16s(dkl + j * 16, Kl + grow + j * 8);
                cp16s(dvh + j * 16, Vh + grow + j * 8);
                cp16s(dvl + j * 16, Vl + grow + j * 8);
            }
        }
        cp_commit();
        cp_wait0();
        __syncthreads();

        // transpose V -> T ([key][d] -> [d][key])
#pragma unroll
        for (int it = 0; it < 16; it++) {
            int idx = tid + it * 128;           // 0..2047
            int key = idx & 63, dp = idx >> 6;  // dp: d-pair 0..31
            uint32_t wh = sVh32[key * TW + dp];
            uint32_t wl = sVl32[key * TW + dp];
            __nv_bfloat162 bh = *(__nv_bfloat162*)&wh;
            __nv_bfloat162 bl = *(__nv_bfloat162*)&wl;
            sTh[(2 * dp) * 72 + key] = bh.x;
            sTh[(2 * dp + 1) * 72 + key] = bh.y;
            sTl[(2 * dp) * 72 + key] = bl.x;
            sTl[(2 * dp + 1) * 72 + key] = bl.y;
        }

        // ---- S = Q K^T (3-term split) ----
        float s[8][4];
#pragma unroll
        for (int j = 0; j < 8; j++)
#pragma unroll
            for (int r = 0; r < 4; r++) s[j][r] = 0.0f;

#pragma unroll
        for (int t = 0; t < 4; t++) {
            uint32_t fqh[4], fql[4];
            int r0 = (warp * 16 + g) * TW + t * 8 + tig;
            int r1 = r0 + 8 * TW;
            fqh[0] = sQh[r0]; fqh[1] = sQh[r1]; fqh[2] = sQh[r0 + 4]; fqh[3] = sQh[r1 + 4];
            fql[0] = sQl[r0]; fql[1] = sQl[r1]; fql[2] = sQl[r0 + 4]; fql[3] = sQl[r1 + 4];
#pragma unroll
            for (int j = 0; j < 8; j++) {
                int n = (j * 8 + g) * TW + t * 8 + tig;
                uint32_t fkh[2] = { sKh[n], sKh[n + 4] };
                uint32_t fkl[2] = { sKl[n], sKl[n + 4] };
                mma16816(s[j], fqh, fkh);
                mma16816(s[j], fqh, fkl);
                mma16816(s[j], fql, fkh);
            }
        }
        __syncthreads();   // transpose visible to all warps before PV

        // ---- online softmax (rows rA = warp*16+g, rB = rA+8) ----
        float mxA = -1e30f, mxB = -1e30f;
#pragma unroll
        for (int j = 0; j < 8; j++) {
            mxA = fmaxf(mxA, fmaxf(s[j][0], s[j][1]));
            mxB = fmaxf(mxB, fmaxf(s[j][2], s[j][3]));
        }
        mxA = fmaxf(mxA, __shfl_xor_sync(0xffffffffu, mxA, 1));
        mxA = fmaxf(mxA, __shfl_xor_sync(0xffffffffu, mxA, 2));
        mxB = fmaxf(mxB, __shfl_xor_sync(0xffffffffu, mxB, 1));
        mxB = fmaxf(mxB, __shfl_xor_sync(0xffffffffu, mxB, 2));
        float nmA = fmaxf(mA, mxA), nmB = fmaxf(mB, mxB);
        float corrA = __expf(mA - nmA), corrB = __expf(mB - nmB);
        float psA = 0.0f, psB = 0.0f;
#pragma unroll
        for (int j = 0; j < 8; j++) {
            s[j][0] = __expf(s[j][0] - nmA); psA += s[j][0];
            s[j][1] = __expf(s[j][1] - nmA); psA += s[j][1];
            s[j][2] = __expf(s[j][2] - nmB); psB += s[j][2];
            s[j][3] = __expf(s[j][3] - nmB); psB += s[j][3];
        }
        psA += __shfl_xor_sync(0xffffffffu, psA, 1);
        psA += __shfl_xor_sync(0xffffffffu, psA, 2);
        psB += __shfl_xor_sync(0xffffffffu, psB, 1);
        psB += __shfl_xor_sync(0xffffffffu, psB, 2);
        lA = lA * corrA + psA; mA = nmA;
        lB = lB * corrB + psB; mB = nmB;
#pragma unroll
        for (int j = 0; j < 8; j++) {
            o[j][0] *= corrA; o[j][1] *= corrA;
            o[j][2] *= corrB; o[j][3] *= corrB;
        }

        // ---- PV (P from registers; 3-term split) ----
#pragma unroll
        for (int t = 0; t < 4; t++) {
            uint32_t pah[4], pal[4];
            split2(s[2*t][0],   s[2*t][1],   pah[0], pal[0]);
            split2(s[2*t][2],   s[2*t][3],   pah[1], pal[1]);
            split2(s[2*t+1][0], s[2*t+1][1], pah[2], pal[2]);
            split2(s[2*t+1][2], s[2*t+1][3], pah[3], pal[3]);
#pragma unroll
            for (int j = 0; j < 8; j++) {
                int n = (j * 8 + g) * TW + t * 8 + tig;
                uint32_t fvh[2] = { sTh32[n], sTh32[n + 4] };
                uint32_t fvl[2] = { sTl32[n], sTl32[n + 4] };
                mma16816(o[j], pah, fvh);
                mma16816(o[j], pah, fvl);
                mma16816(o[j], pal, fvh);
            }
        }
    }

    // ---- epilogue: normalize, split, store bf16 hi/lo ----
    float invA = 1.0f / lA, invB = 1.0f / lB;
    const size_t tokA = (size_t)(b * 1024 + q0 + warp * 16 + g);
    const size_t tokB = tokA + 8;
#pragma unroll
    for (int j = 0; j < 8; j++) {
        int col = h * 64 + j * 8 + tig * 2;
        uint32_t hw, lw;
        split2(o[j][0] * invA, o[j][1] * invA, hw, lw);
        ((uint32_t*)Oh)[(tokA * 1024 + col) >> 1] = hw;
        ((uint32_t*)Ol)[(tokA * 1024 + col) >> 1] = lw;
        split2(o[j][2] * invB, o[j][3] * invB, hw, lw);
        ((uint32_t*)Oh)[(tokB * 1024 + col) >> 1] = hw;
        ((uint32_t*)Ol)[(tokB * 1024 + col) >> 1] = lw;
    }
}

// ---------------------------------------------------------------------------
extern "C" void kernel_launch(void* const* d_in, const int* in_sizes, int n_in,
                              void* d_out, int out_size)
{
    const float* q  = (const float*)d_in[0];
    const float* k  = (const float*)d_in[1];
    const float* v  = (const float*)d_in[2];
    const float* Wq = (const float*)d_in[3];
    const float* bq = (const float*)d_in[4];
    const float* Wk = (const float*)d_in[5];
    const float* bk = (const float*)d_in[6];
    const float* Wv = (const float*)d_in[7];
    const float* bv = (const float*)d_in[8];
    const float* Wo = (const float*)d_in[9];
    const float* bo = (const float*)d_in[10];
    float* out = (float*)d_out;

    float2* gr; cudaGetSymbolAddress((void**)&gr, g_rope);
    __nv_bfloat16* ah; cudaGetSymbolAddress((void**)&ah, g_ah);
    __nv_bfloat16* al; cudaGetSymbolAddress((void**)&al, g_al);
    __nv_bfloat16* wh; cudaGetSymbolAddress((void**)&wh, g_wh);
    __nv_bfloat16* wl; cudaGetSymbolAddress((void**)&wl, g_wl);
    __nv_bfloat16* qh; cudaGetSymbolAddress((void**)&qh, g_qh);
    __nv_bfloat16* ql; cudaGetSymbolAddress((void**)&ql, g_ql);
    __nv_bfloat16* kh; cudaGetSymbolAddress((void**)&kh, g_kh);
    __nv_bfloat16* kl; cudaGetSymbolAddress((void**)&kl, g_kl);
    __nv_bfloat16* vh; cudaGetSymbolAddress((void**)&vh, g_vh);
    __nv_bfloat16* vl; cudaGetSymbolAddress((void**)&vl, g_vl);

    cudaFuncSetAttribute(mma_gemm_kernel, cudaFuncAttributeMaxDynamicSharedMemorySize, GSMEM);
    cudaFuncSetAttribute(attn_mma_kernel, cudaFuncAttributeMaxDynamicSharedMemorySize, ASMEM);

    const size_t AD = (size_t)MT * DD;
    const size_t WD = (size_t)DD * DD;

    // 0) RoPE table + weight converts
    rope_table_kernel<<<1024 * 32 / 256, 256>>>(gr);
    convw_kernel<<<dim3(32, 32, 4), 256>>>(Wq, Wk, Wv, Wo, wh, wl);

    // 1) input activation converts
    conva_kernel<<<AD / 1024, 256>>>(q, ah + 0 * AD, al + 0 * AD);
    conva_kernel<<<AD / 1024, 256>>>(k, ah + 1 * AD, al + 1 * AD);
    conva_kernel<<<AD / 1024, 256>>>(v, ah + 2 * AD, al + 2 * AD);

    // 2) projections -> split bf16 (Q: rope + 1/8 scale; K: rope; V: plain)
    dim3 ggrid(16, 32);
    mma_gemm_kernel<<<ggrid, 256, GSMEM>>>(ah + 0 * AD, al + 0 * AD, wh + 0 * WD, wl + 0 * WD, bq,
                                           (float*)0, qh, ql, gr, 1, 0.125f);
    mma_gemm_kernel<<<ggrid, 256, GSMEM>>>(ah + 1 * AD, al + 1 * AD, wh + 1 * WD, wl + 1 * WD, bk,
                                           (float*)0, kh, kl, gr, 1, 1.0f);
    mma_gemm_kernel<<<ggrid, 256, GSMEM>>>(ah + 2 * AD, al + 2 * AD, wh + 2 * WD, wl + 2 * WD, bv,
                                           (float*)0, vh, vl, gr, 0, 1.0f);

    // 3) mma attention -> split bf16 into slot 0
    dim3 agrid(16, NH, NB);
    attn_mma_kernel<<<agrid, 128, ASMEM>>>(qh, ql, kh, kl, vh, vl, ah + 0 * AD, al + 0 * AD);

    // 4) output projection -> fp32 d_out
    mma_gemm_kernel<<<ggrid, 256, GSMEM>>>(ah + 0 * AD, al + 0 * AD, wh + 3 * WD, wl + 3 * WD, bo,
                                           out, (__nv_bfloat16*)0, (__nv_bfloat16*)0, gr, 0, 1.0f);
}

// round 15
// speedup vs baseline: 2.2008x; 1.1184x over previous
#include <cuda_runtime.h>
#include <cuda_bf16.h>
#include <stdint.h>
#include <math.h>

#define NB 4
#define SS 1024
#define DD 1024
#define NH 16
#define MT (NB*SS)   // 4096 rows

// ---------------------------------------------------------------------------
// Scratch (__device__ globals; no allocation allowed)
// ---------------------------------------------------------------------------
__device__ float2 g_rope[1024*32];                 // [pos][freq] -> (cos,sin)
__device__ __nv_bfloat16 g_ah[3][MT*DD];           // input splits (q,k,v); slot0 reused for attn-out
__device__ __nv_bfloat16 g_al[3][MT*DD];
__device__ __nv_bfloat16 g_wh[4][DD*DD];           // weight hi, TRANSPOSED [n][k]
__device__ __nv_bfloat16 g_wl[4][DD*DD];           // weight lo, TRANSPOSED [n][k]
__device__ __nv_bfloat16 g_qh[MT*DD], g_ql[MT*DD]; // projected Q (rope, x0.125) hi/lo
__device__ __nv_bfloat16 g_kh[MT*DD], g_kl[MT*DD]; // projected K (rope) hi/lo
__device__ __nv_bfloat16 g_vh[MT*DD], g_vl[MT*DD]; // projected V hi/lo (token-major)
__device__ __nv_bfloat16 g_vth[MT*DD], g_vtl[MT*DD]; // V transposed: [(b*16+h)*64+d][token]

// ---------------------------------------------------------------------------
// helpers
// ---------------------------------------------------------------------------
__device__ __forceinline__ void cp16s(uint32_t s, const void* g) {
    asm volatile("cp.async.ca.shared.global [%0], [%1], 16;\n" :: "r"(s), "l"(g));
}
__device__ __forceinline__ void cp_commit() { asm volatile("cp.async.commit_group;\n"); }
__device__ __forceinline__ void cp_wait1()  { asm volatile("cp.async.wait_group 1;\n"); }
__device__ __forceinline__ void cp_wait0()  { asm volatile("cp.async.wait_group 0;\n"); }
__device__ __forceinline__ uint32_t smem_u32(const void* p) {
    uint32_t a;
    asm("{ .reg .u64 t; cvta.to.shared.u64 t, %1; cvt.u32.u64 %0, t; }" : "=r"(a) : "l"(p));
    return a;
}
__device__ __forceinline__ void mma16816(float* c, const uint32_t* a, const uint32_t* b) {
    asm volatile("mma.sync.aligned.m16n8k16.row.col.f32.bf16.bf16.f32 "
        "{%0,%1,%2,%3}, {%4,%5,%6,%7}, {%8,%9}, {%0,%1,%2,%3};"
        : "+f"(c[0]), "+f"(c[1]), "+f"(c[2]), "+f"(c[3])
        : "r"(a[0]), "r"(a[1]), "r"(a[2]), "r"(a[3]), "r"(b[0]), "r"(b[1]));
}
__device__ __forceinline__ void split2(float a, float b, uint32_t& hi, uint32_t& lo) {
    __nv_bfloat16 ha = __float2bfloat16(a), hb = __float2bfloat16(b);
    __nv_bfloat16 la = __float2bfloat16(a - __bfloat162float(ha));
    __nv_bfloat16 lb = __float2bfloat16(b - __bfloat162float(hb));
    __nv_bfloat162 H = __halves2bfloat162(ha, hb), L = __halves2bfloat162(la, lb);
    hi = *(uint32_t*)&H; lo = *(uint32_t*)&L;
}

// ---------------------------------------------------------------------------
// RoPE table (reference quirk: pos = (s*16+h) & 1023 applied at use site)
// ---------------------------------------------------------------------------
__global__ __launch_bounds__(256) void rope_table_kernel(float2* __restrict__ tab)
{
    int idx = blockIdx.x * 256 + threadIdx.x;
    int i = idx & 31;
    int pos = idx >> 5;
    const double LOG1E4 = 9.210340371976184;
    double inv = exp(-((double)i / 32.0) * LOG1E4);
    double ang = (double)pos * inv;
    tab[idx] = make_float2((float)cos(ang), (float)sin(ang));
}

// ---------------------------------------------------------------------------
// Convert activations (q,k,v selected by blockIdx.z): fp32 -> bf16 hi+lo
// ---------------------------------------------------------------------------
__global__ __launch_bounds__(256) void conva_kernel(
    const float* __restrict__ q, const float* __restrict__ k, const float* __restrict__ v,
    __nv_bfloat16* __restrict__ hi_base, __nv_bfloat16* __restrict__ lo_base)
{
    const size_t AD = (size_t)MT * DD;
    const float* src = (blockIdx.z == 0) ? q : (blockIdx.z == 1) ? k : v;
    __nv_bfloat16* hi = hi_base + blockIdx.z * AD;
    __nv_bfloat16* lo = lo_base + blockIdx.z * AD;
    int i = (blockIdx.x * 256 + threadIdx.x) * 4;
    float4 a = *(const float4*)&src[i];
    uint32_t h0, l0, h1, l1;
    split2(a.x, a.y, h0, l0);
    split2(a.z, a.w, h1, l1);
    uint32_t* H = (uint32_t*)&hi[i];
    uint32_t* L = (uint32_t*)&lo[i];
    H[0] = h0; H[1] = h1; L[0] = l0; L[1] = l1;
}

// Single convert (attention output)
__global__ __launch_bounds__(256) void conva1_kernel(
    const float* __restrict__ src, __nv_bfloat16* __restrict__ hi, __nv_bfloat16* __restrict__ lo)
{
    int i = (blockIdx.x * 256 + threadIdx.x) * 4;
    float4 a = *(const float4*)&src[i];
    uint32_t h0, l0, h1, l1;
    split2(a.x, a.y, h0, l0);
    split2(a.z, a.w, h1, l1);
    uint32_t* H = (uint32_t*)&hi[i];
    uint32_t* L = (uint32_t*)&lo[i];
    H[0] = h0; H[1] = h1; L[0] = l0; L[1] = l1;
}

// ---------------------------------------------------------------------------
// Convert + transpose weights: W[k][n] fp32 -> Wt_hi/lo[n][k] bf16
// ---------------------------------------------------------------------------
__global__ __launch_bounds__(256) void convw_kernel(
    const float* __restrict__ Wq, const float* __restrict__ Wk,
    const float* __restrict__ Wv, const float* __restrict__ Wo,
    __nv_bfloat16* __restrict__ th, __nv_bfloat16* __restrict__ tl)
{
    __shared__ float t[32][33];
    const float* W = (blockIdx.z == 0) ? Wq : (blockIdx.z == 1) ? Wk : (blockIdx.z == 2) ? Wv : Wo;
    __nv_bfloat16* oh = th + (size_t)blockIdx.z * DD * DD;
    __nv_bfloat16* ol = tl + (size_t)blockIdx.z * DD * DD;
    int n0 = blockIdx.x * 32, k0 = blockIdx.y * 32;
    int tx = threadIdx.x & 31, ty = threadIdx.x >> 5;
#pragma unroll
    for (int r = 0; r < 32; r += 8)
        t[ty + r][tx] = W[(size_t)(k0 + ty + r) * DD + n0 + tx];
    __syncthreads();
#pragma unroll
    for (int r = 0; r < 32; r += 8) {
        float v = t[tx][ty + r];
        __nv_bfloat16 h = __float2bfloat16(v);
        __nv_bfloat16 l = __float2bfloat16(v - __bfloat162float(h));
        size_t o = (size_t)(n0 + ty + r) * DD + k0 + tx;
        oh[o] = h; ol[o] = l;
    }
}

// ---------------------------------------------------------------------------
// Transpose projected V: [token][h*64+d] -> [(b*16+h)*64+d][token]
// grid (32 s-tiles, 2 d-tiles, 64 bh), 256 threads
// ---------------------------------------------------------------------------
__global__ __launch_bounds__(256) void transv_kernel(
    const __nv_bfloat16* __restrict__ Vh, const __nv_bfloat16* __restrict__ Vl,
    __nv_bfloat16* __restrict__ Th, __nv_bfloat16* __restrict__ Tl)
{
    __shared__ __nv_bfloat16 th[32][34];
    __shared__ __nv_bfloat16 tl[32][34];
    int z = blockIdx.z;            // b*16+h
    int b = z >> 4, h = z & 15;
    int s0 = blockIdx.x * 32, d0 = blockIdx.y * 32;
    int tx = threadIdx.x & 31, ty = threadIdx.x >> 5;
#pragma unroll
    for (int r = 0; r < 32; r += 8) {
        size_t gi = (size_t)(b * 1024 + s0 + ty + r) * 1024 + h * 64 + d0 + tx;
        th[ty + r][tx] = Vh[gi];
        tl[ty + r][tx] = Vl[gi];
    }
    __syncthreads();
#pragma unroll
    for (int r = 0; r < 32; r += 8) {
        size_t go = ((size_t)z * 64 + d0 + ty + r) * 1024 + s0 + tx;
        Th[go] = th[tx][ty + r];
        Tl[go] = tl[tx][ty + r];
    }
}

// ---------------------------------------------------------------------------
// Warp-MMA bf16-split GEMM body. CTA 128(M) x 64(N=head). 8 warps (4Mx2N).
// ---------------------------------------------------------------------------
#define SAP 10240
#define SBP 5120
#define STG (2*SAP + 2*SBP)
#define GSMEM (2*STG)           // 61440

__device__ __forceinline__ void gemm_body(
    const __nv_bfloat16* __restrict__ Ah, const __nv_bfloat16* __restrict__ Al,
    const __nv_bfloat16* __restrict__ Bh, const __nv_bfloat16* __restrict__ Bl,
    const float* __restrict__ bias,
    float* __restrict__ Cf, __nv_bfloat16* __restrict__ Ch, __nv_bfloat16* __restrict__ Cl,
    const float2* __restrict__ rope, int do_rope, float scale, char* dsm)
{
    const uint32_t sb = smem_u32(dsm);
    const int tid  = threadIdx.x;
    const int lane = tid & 31;
    const int warp = tid >> 5;
    const int wm = warp >> 1, wn = warp & 1;
    const int g = lane >> 2, tig = lane & 3;
    const int bm = blockIdx.y * 128;
    const int bn = blockIdx.x * 64;

    const int ar  = tid >> 1;
    const int ah2 = (tid & 1) * 16;
    const int br  = tid >> 2;
    const int bq4 = (tid & 3) * 8;

#define LOAD_STAGE(c, buf) do {                                                   \
        uint32_t base = sb + (buf) * STG;                                         \
        int k0 = (c) * 32;                                                        \
        const __nv_bfloat16* pah = Ah + (size_t)(bm + ar) * 1024 + k0 + ah2;      \
        const __nv_bfloat16* pal = Al + (size_t)(bm + ar) * 1024 + k0 + ah2;      \
        uint32_t ao = base + (uint32_t)ar * 80u + (uint32_t)(ah2 * 2);            \
        cp16s(ao,              pah);                                              \
        cp16s(ao + 16,         pah + 8);                                          \
        cp16s(ao + SAP,        pal);                                              \
        cp16s(ao + SAP + 16,   pal + 8);                                          \
        const __nv_bfloat16* pbh = Bh + (size_t)(bn + br) * 1024 + k0 + bq4;      \
        const __nv_bfloat16* pbl = Bl + (size_t)(bn + br) * 1024 + k0 + bq4;      \
        uint32_t bo = base + 2*SAP + (uint32_t)br * 80u + (uint32_t)(bq4 * 2);    \
        cp16s(bo,        pbh);                                                    \
        cp16s(bo + SBP,  pbl);                                                    \
    } while (0)

    float c_[2][4][4];
#pragma unroll
    for (int mt = 0; mt < 2; mt++)
#pragma unroll
        for (int nt = 0; nt < 4; nt++)
#pragma unroll
            for (int r = 0; r < 4; r++) c_[mt][nt][r] = 0.0f;

    LOAD_STAGE(0, 0);
    cp_commit();

    for (int c = 0; c < 32; c++) {
        if (c + 1 < 32) { LOAD_STAGE(c + 1, (c + 1) & 1); cp_commit(); cp_wait1(); }
        else            { cp_wait0(); }
        __syncthreads();

        const uint32_t* wAh = (const uint32_t*)(dsm + (c & 1) * STG);
        const uint32_t* wAl = (const uint32_t*)(dsm + (c & 1) * STG + SAP);
        const uint32_t* wBh = (const uint32_t*)(dsm + (c & 1) * STG + 2 * SAP);
        const uint32_t* wBl = (const uint32_t*)(dsm + (c & 1) * STG + 2 * SAP + SBP);

#pragma unroll
        for (int kk = 0; kk < 2; kk++) {
            const int ko = kk * 8;
            uint32_t fah[2][4], fal[2][4];
#pragma unroll
            for (int mt = 0; mt < 2; mt++) {
                int r0 = (wm * 32 + mt * 16 + g) * 20 + ko + tig;
                int r1 = (wm * 32 + mt * 16 + g + 8) * 20 + ko + tig;
                fah[mt][0] = wAh[r0];     fah[mt][1] = wAh[r1];
                fah[mt][2] = wAh[r0 + 4]; fah[mt][3] = wAh[r1 + 4];
                fal[mt][0] = wAl[r0];     fal[mt][1] = wAl[r1];
                fal[mt][2] = wAl[r0 + 4]; fal[mt][3] = wAl[r1 + 4];
            }
            uint32_t fbh[4][2], fbl[4][2];
#pragma unroll
            for (int nt = 0; nt < 4; nt++) {
                int n = (wn * 32 + nt * 8 + g) * 20 + ko + tig;
                fbh[nt][0] = wBh[n]; fbh[nt][1] = wBh[n + 4];
                fbl[nt][0] = wBl[n]; fbl[nt][1] = wBl[n + 4];
            }
#pragma unroll
            for (int mt = 0; mt < 2; mt++)
#pragma unroll
                for (int nt = 0; nt < 4; nt++) {
                    mma16816(c_[mt][nt], fah[mt], fbh[nt]);
                    mma16816(c_[mt][nt], fah[mt], fbl[nt]);
                    mma16816(c_[mt][nt], fal[mt], fbh[nt]);
                }
        }
        __syncthreads();
    }
#undef LOAD_STAGE

    const int head = blockIdx.x;
#pragma unroll
    for (int mt = 0; mt < 2; mt++) {
        int row0 = bm + wm * 32 + mt * 16 + g;
        int row1 = row0 + 8;
        int pos0 = 0, pos1 = 0;
        if (do_rope) {
            pos0 = (((row0 & 1023) * 16 + head) & 1023);
            pos1 = (((row1 & 1023) * 16 + head) & 1023);
        }
#pragma unroll
        for (int nt = 0; nt < 4; nt++) {
            int col = bn + wn * 32 + nt * 8 + tig * 2;
            float b0 = bias[col], b1 = bias[col + 1];
            float x0 = c_[mt][nt][0] + b0, x1 = c_[mt][nt][1] + b1;
            float y0 = c_[mt][nt][2] + b0, y1 = c_[mt][nt][3] + b1;
            if (do_rope) {
                int i = wn * 16 + nt * 4 + tig;
                float2 cs0 = rope[pos0 * 32 + i];
                float2 cs1 = rope[pos1 * 32 + i];
                float t0 = x0 * cs0.x - x1 * cs0.y;
                x1 = x0 * cs0.y + x1 * cs0.x; x0 = t0;
                float t1 = y0 * cs1.x - y1 * cs1.y;
                y1 = y0 * cs1.y + y1 * cs1.x; y0 = t1;
            }
            x0 *= scale; x1 *= scale; y0 *= scale; y1 *= scale;
            if (Cf) {
                *(float2*)&Cf[(size_t)row0 * 1024 + col] = make_float2(x0, x1);
                *(float2*)&Cf[(size_t)row1 * 1024 + col] = make_float2(y0, y1);
            } else {
                uint32_t hw, lw;
                split2(x0, x1, hw, lw);
                ((uint32_t*)Ch)[((size_t)row0 * 1024 + col) >> 1] = hw;
                ((uint32_t*)Cl)[((size_t)row0 * 1024 + col) >> 1] = lw;
                split2(y0, y1, hw, lw);
                ((uint32_t*)Ch)[((size_t)row1 * 1024 + col) >> 1] = hw;
                ((uint32_t*)Cl)[((size_t)row1 * 1024 + col) >> 1] = lw;
            }
        }
    }
}

// Fused Q/K/V projection launch: blockIdx.z selects problem
__global__ void __launch_bounds__(256) qkv_gemm_kernel(
    const __nv_bfloat16* __restrict__ ah, const __nv_bfloat16* __restrict__ al,
    const __nv_bfloat16* __restrict__ wh, const __nv_bfloat16* __restrict__ wl,
    const float* __restrict__ bq, const float* __restrict__ bk, const float* __restrict__ bv,
    __nv_bfloat16* __restrict__ qh, __nv_bfloat16* __restrict__ ql,
    __nv_bfloat16* __restrict__ kh, __nv_bfloat16* __restrict__ kl,
    __nv_bfloat16* __restrict__ vh, __nv_bfloat16* __restrict__ vl,
    const float2* __restrict__ rope)
{
    extern __shared__ __align__(16) char dsm[];
    const size_t AD = (size_t)MT * DD;
    const size_t WD = (size_t)DD * DD;
    int z = blockIdx.z;
    const __nv_bfloat16* Ah = ah + z * AD;
    const __nv_bfloat16* Al = al + z * AD;
    const __nv_bfloat16* Bh = wh + z * WD;
    const __nv_bfloat16* Bl = wl + z * WD;
    const float* bias = (z == 0) ? bq : (z == 1) ? bk : bv;
    __nv_bfloat16* Ch = (z == 0) ? qh : (z == 1) ? kh : vh;
    __nv_bfloat16* Cl = (z == 0) ? ql : (z == 1) ? kl : vl;
    int do_rope = (z < 2);
    float scale = (z == 0) ? 0.125f : 1.0f;
    gemm_body(Ah, Al, Bh, Bl, bias, (float*)0, Ch, Cl, rope, do_rope, scale, dsm);
}

// Output projection
__global__ void __launch_bounds__(256) out_gemm_kernel(
    const __nv_bfloat16* __restrict__ Ah, const __nv_bfloat16* __restrict__ Al,
    const __nv_bfloat16* __restrict__ Bh, const __nv_bfloat16* __restrict__ Bl,
    const float* __restrict__ bias, float* __restrict__ Cf)
{
    extern __shared__ __align__(16) char dsm[];
    gemm_body(Ah, Al, Bh, Bl, bias, Cf, (__nv_bfloat16*)0, (__nv_bfloat16*)0,
              (const float2*)0, 0, 1.0f, dsm);
}

// ---------------------------------------------------------------------------
// MMA flash attention: grid (16 qtiles, 16 h, 4 b), 128 threads (4 warps).
// Smem: Qh Ql Kh Kl Th Tl, 6 tiles of 64 rows x 72 bf16 = 55296 B -> 4 CTA/SM.
// T (=V^T [d][key]) loaded directly from pre-transposed g_vt.
// Q fragments hoisted to registers (loop-invariant).
// ---------------------------------------------------------------------------
#define TW 36
#define TB 9216
#define ASMEM (6*TB)   // 55296

__global__ void __launch_bounds__(128) attn_mma_kernel(
    const __nv_bfloat16* __restrict__ Qh, const __nv_bfloat16* __restrict__ Ql,
    const __nv_bfloat16* __restrict__ Kh, const __nv_bfloat16* __restrict__ Kl,
    const __nv_bfloat16* __restrict__ Th, const __nv_bfloat16* __restrict__ Tl,
    __nv_bfloat16* __restrict__ Oh, __nv_bfloat16* __restrict__ Ol)
{
    extern __shared__ __align__(16) char sm_[];
    const uint32_t sb = smem_u32(sm_);
    const int tid  = threadIdx.x;
    const int lane = tid & 31;
    const int warp = tid >> 5;
    const int g = lane >> 2, tig = lane & 3;
    const int h = blockIdx.y, b = blockIdx.z;
    const int q0 = blockIdx.x * 64;
    const int z = b * 16 + h;

    const int lrow = tid >> 1;                 // 0..63
    const int lhalf = (tid & 1) * 32;          // bf16 units

    // ---- issue Q tile load (group 0) ----
    {
        const __nv_bfloat16* ph = Qh + ((size_t)(b * 1024 + q0 + lrow)) * 1024 + h * 64 + lhalf;
        const __nv_bfloat16* pl = Ql + ((size_t)(b * 1024 + q0 + lrow)) * 1024 + h * 64 + lhalf;
        uint32_t dh = sb + 0 * TB + lrow * 144 + lhalf * 2;
        uint32_t dl = sb + 1 * TB + lrow * 144 + lhalf * 2;
#pragma unroll
        for (int j = 0; j < 4; j++) {
            cp16s(dh + j * 16, ph + j * 8);
            cp16s(dl + j * 16, pl + j * 8);
        }
    }
    cp_commit();

    // ---- issue K/T tile 0 load (group 1) ----
#define LOAD_KT(kt) do {                                                            \
        size_t grow = ((size_t)(b * 1024 + (kt) * 64 + lrow)) * 1024 + h * 64 + lhalf; \
        uint32_t dkh = sb + 2 * TB + lrow * 144 + lhalf * 2;                        \
        uint32_t dkl = sb + 3 * TB + lrow * 144 + lhalf * 2;                        \
        size_t trow = ((size_t)z * 64 + lrow) * 1024 + (kt) * 64 + lhalf;           \
        uint32_t dth = sb + 4 * TB + lrow * 144 + lhalf * 2;                        \
        uint32_t dtl = sb + 5 * TB + lrow * 144 + lhalf * 2;                        \
        _Pragma("unroll")                                                           \
        for (int j = 0; j < 4; j++) {                                               \
            cp16s(dkh + j * 16, Kh + grow + j * 8);                                 \
            cp16s(dkl + j * 16, Kl + grow + j * 8);                                 \
            cp16s(dth + j * 16, Th + trow + j * 8);                                 \
            cp16s(dtl + j * 16, Tl + trow + j * 8);                                 \
        }                                                                           \
    } while (0)

    LOAD_KT(0);
    cp_commit();

    const uint32_t* sQh = (const uint32_t*)(sm_ + 0 * TB);
    const uint32_t* sQl = (const uint32_t*)(sm_ + 1 * TB);
    const uint32_t* sKh = (const uint32_t*)(sm_ + 2 * TB);
    const uint32_t* sKl = (const uint32_t*)(sm_ + 3 * TB);
    const uint32_t* sTh32 = (const uint32_t*)(sm_ + 4 * TB);
    const uint32_t* sTl32 = (const uint32_t*)(sm_ + 5 * TB);

    // ---- Q ready: hoist fragments to registers ----
    cp_wait1();
    __syncthreads();
    uint32_t fqh[4][4], fql[4][4];
#pragma unroll
    for (int t = 0; t < 4; t++) {
        int r0 = (warp * 16 + g) * TW + t * 8 + tig;
        int r1 = r0 + 8 * TW;
        fqh[t][0] = sQh[r0]; fqh[t][1] = sQh[r1]; fqh[t][2] = sQh[r0 + 4]; fqh[t][3] = sQh[r1 + 4];
        fql[t][0] = sQl[r0]; fql[t][1] = sQl[r1]; fql[t][2] = sQl[r0 + 4]; fql[t][3] = sQl[r1 + 4];
    }

    float mA = -1e30f, mB = -1e30f, lA = 0.0f, lB = 0.0f;
    float o[8][4];
#pragma unroll
    for (int j = 0; j < 8; j++)
#pragma unroll
        for (int r = 0; r < 4; r++) o[j][r] = 0.0f;

    for (int kt = 0; kt < 16; kt++) {
        cp_wait0();
        __syncthreads();

        // ---- S = Q K^T (3-term split) ----
        float s[8][4];
#pragma unroll
        for (int j = 0; j < 8; j++)
#pragma unroll
            for (int r = 0; r < 4; r++) s[j][r] = 0.0f;
#pragma unroll
        for (int t = 0; t < 4; t++) {
#pragma unroll
            for (int j = 0; j < 8; j++) {
                int n = (j * 8 + g) * TW + t * 8 + tig;
                uint32_t fkh[2] = { sKh[n], sKh[n + 4] };
                uint32_t fkl[2] = { sKl[n], sKl[n + 4] };
                mma16816(s[j], fqh[t], fkh);
                mma16816(s[j], fqh[t], fkl);
                mma16816(s[j], fql[t], fkh);
            }
        }

        // ---- online softmax ----
        float mxA = -1e30f, mxB = -1e30f;
#pragma unroll
        for (int j = 0; j < 8; j++) {
            mxA = fmaxf(mxA, fmaxf(s[j][0], s[j][1]));
            mxB = fmaxf(mxB, fmaxf(s[j][2], s[j][3]));
        }
        mxA = fmaxf(mxA, __shfl_xor_sync(0xffffffffu, mxA, 1));
        mxA = fmaxf(mxA, __shfl_xor_sync(0xffffffffu, mxA, 2));
        mxB = fmaxf(mxB, __shfl_xor_sync(0xffffffffu, mxB, 1));
        mxB = fmaxf(mxB, __shfl_xor_sync(0xffffffffu, mxB, 2));
        float nmA = fmaxf(mA, mxA), nmB = fmaxf(mB, mxB);
        float corrA = __expf(mA - nmA), corrB = __expf(mB - nmB);
        float psA = 0.0f, psB = 0.0f;
#pragma unroll
        for (int j = 0; j < 8; j++) {
            s[j][0] = __expf(s[j][0] - nmA); psA += s[j][0];
            s[j][1] = __expf(s[j][1] - nmA); psA += s[j][1];
            s[j][2] = __expf(s[j][2] - nmB); psB += s[j][2];
            s[j][3] = __expf(s[j][3] - nmB); psB += s[j][3];
        }
        psA += __shfl_xor_sync(0xffffffffu, psA, 1);
        psA += __shfl_xor_sync(0xffffffffu, psA, 2);
        psB += __shfl_xor_sync(0xffffffffu, psB, 1);
        psB += __shfl_xor_sync(0xffffffffu, psB, 2);
        lA = lA * corrA + psA; mA = nmA;
        lB = lB * corrB + psB; mB = nmB;
#pragma unroll
        for (int j = 0; j < 8; j++) {
            o[j][0] *= corrA; o[j][1] *= corrA;
            o[j][2] *= corrB; o[j][3] *= corrB;
        }

        // ---- PV (P from registers; 3-term split) ----
#pragma unroll
        for (int t = 0; t < 4; t++) {
            uint32_t pah[4], pal[4];
            split2(s[2*t][0],   s[2*t][1],   pah[0], pal[0]);
            split2(s[2*t][2],   s[2*t][3],   pah[1], pal[1]);
            split2(s[2*t+1][0], s[2*t+1][1], pah[2], pal[2]);
            split2(s[2*t+1][2], s[2*t+1][3], pah[3], pal[3]);
#pragma unroll
            for (int j = 0; j < 8; j++) {
                int n = (j * 8 + g) * TW + t * 8 + tig;
                uint32_t fvh[2] = { sTh32[n], sTh32[n + 4] };
                uint32_t fvl[2] = { sTl32[n], sTl32[n + 4] };
                mma16816(o[j], pah, fvh);
                mma16816(o[j], pah, fvl);
                mma16816(o[j], pal, fvh);
            }
        }

        __syncthreads();        // all warps done with K/T before refill
        if (kt + 1 < 16) { LOAD_KT(kt + 1); cp_commit(); }
    }
#undef LOAD_KT

    // ---- epilogue: normalize, split, store bf16 hi/lo ----
    float invA = 1.0f / lA, invB = 1.0f / lB;
    const size_t tokA = (size_t)(b * 1024 + q0 + warp * 16 + g);
    const size_t tokB = tokA + 8;
#pragma unroll
    for (int j = 0; j < 8; j++) {
        int col = h * 64 + j * 8 + tig * 2;
        uint32_t hw, lw;
        split2(o[j][0] * invA, o[j][1] * invA, hw, lw);
        ((uint32_t*)Oh)[(tokA * 1024 + col) >> 1] = hw;
        ((uint32_t*)Ol)[(tokA * 1024 + col) >> 1] = lw;
        split2(o[j][2] * invB, o[j][3] * invB, hw, lw);
        ((uint32_t*)Oh)[(tokB * 1024 + col) >> 1] = hw;
        ((uint32_t*)Ol)[(tokB * 1024 + col) >> 1] = lw;
    }
}

// ---------------------------------------------------------------------------
extern "C" void kernel_launch(void* const* d_in, const int* in_sizes, int n_in,
                              void* d_out, int out_size)
{
    const float* q  = (const float*)d_in[0];
    const float* k  = (const float*)d_in[1];
    const float* v  = (const float*)d_in[2];
    const float* Wq = (const float*)d_in[3];
    const float* bq = (const float*)d_in[4];
    const float* Wk = (const float*)d_in[5];
    const float* bk = (const float*)d_in[6];
    const float* Wv = (const float*)d_in[7];
    const float* bv = (const float*)d_in[8];
    const float* Wo = (const float*)d_in[9];
    const float* bo = (const float*)d_in[10];
    float* out = (float*)d_out;

    float2* gr; cudaGetSymbolAddress((void**)&gr, g_rope);
    __nv_bfloat16* ah; cudaGetSymbolAddress((void**)&ah, g_ah);
    __nv_bfloat16* al; cudaGetSymbolAddress((void**)&al, g_al);
    __nv_bfloat16* wh; cudaGetSymbolAddress((void**)&wh, g_wh);
    __nv_bfloat16* wl; cudaGetSymbolAddress((void**)&wl, g_wl);
    __nv_bfloat16* qh; cudaGetSymbolAddress((void**)&qh, g_qh);
    __nv_bfloat16* ql; cudaGetSymbolAddress((void**)&ql, g_ql);
    __nv_bfloat16* kh; cudaGetSymbolAddress((void**)&kh, g_kh);
    __nv_bfloat16* kl; cudaGetSymbolAddress((void**)&kl, g_kl);
    __nv_bfloat16* vh; cudaGetSymbolAddress((void**)&vh, g_vh);
    __nv_bfloat16* vl; cudaGetSymbolAddress((void**)&vl, g_vl);
    __nv_bfloat16* vth; cudaGetSymbolAddress((void**)&vth, g_vth);
    __nv_bfloat16* vtl; cudaGetSymbolAddress((void**)&vtl, g_vtl);

    cudaFuncSetAttribute(qkv_gemm_kernel, cudaFuncAttributeMaxDynamicSharedMemorySize, GSMEM);
    cudaFuncSetAttribute(out_gemm_kernel, cudaFuncAttributeMaxDynamicSharedMemorySize, GSMEM);
    cudaFuncSetAttribute(attn_mma_kernel, cudaFuncAttributeMaxDynamicSharedMemorySize, ASMEM);

    const size_t AD = (size_t)MT * DD;
    const size_t WD = (size_t)DD * DD;

    // 0) RoPE table + weight converts + input converts
    rope_table_kernel<<<1024 * 32 / 256, 256>>>(gr);
    convw_kernel<<<dim3(32, 32, 4), 256>>>(Wq, Wk, Wv, Wo, wh, wl);
    conva_kernel<<<dim3(AD / 1024, 1, 3), 256>>>(q, k, v, ah, al);

    // 1) fused Q/K/V projections -> split bf16
    dim3 ggrid(16, 32, 3);
    qkv_gemm_kernel<<<ggrid, 256, GSMEM>>>(ah, al, wh, wl, bq, bk, bv,
                                           qh, ql, kh, kl, vh, vl, gr);

    // 2) transpose V for attention B-operand
    transv_kernel<<<dim3(32, 2, 64), 256>>>(vh, vl, vth, vtl);

    // 3) mma attention -> split bf16 into slot 0
    dim3 agrid(16, NH, NB);
    attn_mma_kernel<<<agrid, 128, ASMEM>>>(qh, ql, kh, kl, vth, vtl, ah + 0 * AD, al + 0 * AD);

    // 4) output projection -> fp32 d_out
    dim3 ogrid(16, 32, 1);
    out_gemm_kernel<<<ogrid, 256, GSMEM>>>(ah + 0 * AD, al + 0 * AD, wh + 3 * WD, wl + 3 * WD, bo, out);
}

// round 16
// speedup vs baseline: 2.3874x; 1.0848x over previous
#include <cuda_runtime.h>
#include <stdint.h>
#include <math.h>

#define NB 4
#define SS 1024
#define DD 1024
#define NH 16
#define MT (NB*SS)   // 4096 rows

// ---------------------------------------------------------------------------
// Scratch (__device__ globals; no allocation allowed). All fp32, tf32-rounded.
// ---------------------------------------------------------------------------
__device__ float2 g_rope[1024*32];     // [pos][freq] -> (cos,sin)
__device__ float g_x[3][MT*DD];        // rounded inputs q,k,v; slot0 reused for attn-out
__device__ float g_wt[4][DD*DD];       // weights transposed [n][k], tf32-rounded
__device__ float g_pq[MT*DD];          // projected Q (rope, x0.125)
__device__ float g_pk[MT*DD];          // projected K (rope)
__device__ float g_pv[MT*DD];          // projected V
__device__ float g_vt[MT*DD];          // V transposed: [(b*16+h)*64+d][token]

// ---------------------------------------------------------------------------
// helpers
// ---------------------------------------------------------------------------
__device__ __forceinline__ void cp16s(uint32_t s, const void* g) {
    asm volatile("cp.async.ca.shared.global [%0], [%1], 16;\n" :: "r"(s), "l"(g));
}
__device__ __forceinline__ void cp_commit() { asm volatile("cp.async.commit_group;\n"); }
__device__ __forceinline__ void cp_wait1()  { asm volatile("cp.async.wait_group 1;\n"); }
__device__ __forceinline__ void cp_wait0()  { asm volatile("cp.async.wait_group 0;\n"); }
__device__ __forceinline__ uint32_t smem_u32(const void* p) {
    uint32_t a;
    asm("{ .reg .u64 t; cvta.to.shared.u64 t, %1; cvt.u32.u64 %0, t; }" : "=r"(a) : "l"(p));
    return a;
}
// round fp32 -> tf32 (round-to-nearest-even on 10-bit mantissa), returned as fp32 bits
__device__ __forceinline__ float tf32r(float x) {
    uint32_t r;
    asm("cvt.rna.tf32.f32 %0, %1;" : "=r"(r) : "f"(x));
    return __uint_as_float(r);
}
// Warp MMA: D(m16n8) += A(m16k8,row) * B(k8n8,col)  tf32 in (b32 regs), f32 accum
__device__ __forceinline__ void mmatf32(float* c, const uint32_t* a, const uint32_t* b) {
    asm volatile("mma.sync.aligned.m16n8k8.row.col.f32.tf32.tf32.f32 "
        "{%0,%1,%2,%3}, {%4,%5,%6,%7}, {%8,%9}, {%0,%1,%2,%3};"
        : "+f"(c[0]), "+f"(c[1]), "+f"(c[2]), "+f"(c[3])
        : "r"(a[0]), "r"(a[1]), "r"(a[2]), "r"(a[3]), "r"(b[0]), "r"(b[1]));
}

// ---------------------------------------------------------------------------
// RoPE table (reference quirk: pos = (s*16+h) & 1023 applied at use site)
// ---------------------------------------------------------------------------
__global__ __launch_bounds__(256) void rope_table_kernel(float2* __restrict__ tab)
{
    int idx = blockIdx.x * 256 + threadIdx.x;
    int i = idx & 31;
    int pos = idx >> 5;
    const double LOG1E4 = 9.210340371976184;
    double inv = exp(-((double)i / 32.0) * LOG1E4);
    double ang = (double)pos * inv;
    tab[idx] = make_float2((float)cos(ang), (float)sin(ang));
}

// ---------------------------------------------------------------------------
// Round inputs to tf32 (q,k,v via blockIdx.z)
// ---------------------------------------------------------------------------
__global__ __launch_bounds__(256) void round_kernel(
    const float* __restrict__ q, const float* __restrict__ k, const float* __restrict__ v,
    float* __restrict__ dst_base)
{
    const size_t AD = (size_t)MT * DD;
    const float* src = (blockIdx.z == 0) ? q : (blockIdx.z == 1) ? k : v;
    float* dst = dst_base + blockIdx.z * AD;
    int i = (blockIdx.x * 256 + threadIdx.x) * 4;
    float4 a = *(const float4*)&src[i];
    a.x = tf32r(a.x); a.y = tf32r(a.y); a.z = tf32r(a.z); a.w = tf32r(a.w);
    *(float4*)&dst[i] = a;
}

// ---------------------------------------------------------------------------
// Transpose + round weights: W[k][n] -> Wt[n][k] (tf32-rounded)
// ---------------------------------------------------------------------------
__global__ __launch_bounds__(256) void convw_kernel(
    const float* __restrict__ Wq, const float* __restrict__ Wk,
    const float* __restrict__ Wv, const float* __restrict__ Wo,
    float* __restrict__ wt)
{
    __shared__ float t[32][33];
    const float* W = (blockIdx.z == 0) ? Wq : (blockIdx.z == 1) ? Wk : (blockIdx.z == 2) ? Wv : Wo;
    float* o = wt + (size_t)blockIdx.z * DD * DD;
    int n0 = blockIdx.x * 32, k0 = blockIdx.y * 32;
    int tx = threadIdx.x & 31, ty = threadIdx.x >> 5;
#pragma unroll
    for (int r = 0; r < 32; r += 8)
        t[ty + r][tx] = W[(size_t)(k0 + ty + r) * DD + n0 + tx];
    __syncthreads();
#pragma unroll
    for (int r = 0; r < 32; r += 8)
        o[(size_t)(n0 + ty + r) * DD + k0 + tx] = tf32r(t[tx][ty + r]);
}

// ---------------------------------------------------------------------------
// Transpose projected V: [token][h*64+d] -> [(b*16+h)*64+d][token]
// ---------------------------------------------------------------------------
__global__ __launch_bounds__(256) void transv_kernel(
    const float* __restrict__ V, float* __restrict__ T)
{
    __shared__ float t[32][33];
    int z = blockIdx.z;            // b*16+h
    int b = z >> 4, h = z & 15;
    int s0 = blockIdx.x * 32, d0 = blockIdx.y * 32;
    int tx = threadIdx.x & 31, ty = threadIdx.x >> 5;
#pragma unroll
    for (int r = 0; r < 32; r += 8)
        t[ty + r][tx] = V[(size_t)(b * 1024 + s0 + ty + r) * 1024 + h * 64 + d0 + tx];
    __syncthreads();
#pragma unroll
    for (int r = 0; r < 32; r += 8)
        T[((size_t)z * 64 + d0 + ty + r) * 1024 + s0 + tx] = t[tx][ty + r];
}

// ---------------------------------------------------------------------------
// tf32 warp-MMA GEMM. CTA 128(M) x 128(N = 2 heads). 256 thr, 8 warps 4Mx2N,
// warp tile 32x64 (mt=2 m16, nt=8 n8). K chunks of 32, 2-stage cp.async.
// Smem rows: 32 floats padded to 36 (bank-conflict-free fragment loads).
// Stage = A(128x36x4=18432) + B(18432) = 36864; double = 73728.
// ---------------------------------------------------------------------------
#define GTILE 18432
#define GSTG  (2*GTILE)
#define GSMEM (2*GSTG)   // 73728

__device__ __forceinline__ void gemm_body(
    const float* __restrict__ A, const float* __restrict__ B,
    const float* __restrict__ bias,
    float* __restrict__ C, const float2* __restrict__ rope,
    int do_rope, float scale, int round_out, char* dsm)
{
    const uint32_t sb = smem_u32(dsm);
    const int tid  = threadIdx.x;
    const int lane = tid & 31;
    const int warp = tid >> 5;
    const int wm = warp >> 1, wn = warp & 1;
    const int g = lane >> 2, tig = lane & 3;
    const int bm = blockIdx.y * 128;
    const int bn = blockIdx.x * 128;

    const int lr   = tid >> 1;         // 0..127 (row for both A and B tiles)
    const int lhf  = (tid & 1);        // half: 16 floats = 64B

#define LOAD_STAGE(c, buf) do {                                                   \
        uint32_t base = sb + (buf) * GSTG;                                        \
        int k0 = (c) * 32;                                                        \
        const float* pa = A + (size_t)(bm + lr) * 1024 + k0 + lhf * 16;           \
        uint32_t ao = base + (uint32_t)lr * 144u + (uint32_t)lhf * 64u;           \
        cp16s(ao,      pa);                                                       \
        cp16s(ao + 16, pa + 4);                                                   \
        cp16s(ao + 32, pa + 8);                                                   \
        cp16s(ao + 48, pa + 12);                                                  \
        const float* pb = B + (size_t)(bn + lr) * 1024 + k0 + lhf * 16;           \
        uint32_t bo = base + GTILE + (uint32_t)lr * 144u + (uint32_t)lhf * 64u;   \
        cp16s(bo,      pb);                                                       \
        cp16s(bo + 16, pb + 4);                                                   \
        cp16s(bo + 32, pb + 8);                                                   \
        cp16s(bo + 48, pb + 12);                                                  \
    } while (0)

    float c_[2][8][4];
#pragma unroll
    for (int mt = 0; mt < 2; mt++)
#pragma unroll
        for (int nt = 0; nt < 8; nt++)
#pragma unroll
            for (int r = 0; r < 4; r++) c_[mt][nt][r] = 0.0f;

    LOAD_STAGE(0, 0);
    cp_commit();

    for (int c = 0; c < 32; c++) {
        if (c + 1 < 32) { LOAD_STAGE(c + 1, (c + 1) & 1); cp_commit(); cp_wait1(); }
        else            { cp_wait0(); }
        __syncthreads();

        const uint32_t* sA = (const uint32_t*)(dsm + (c & 1) * GSTG);
        const uint32_t* sB = (const uint32_t*)(dsm + (c & 1) * GSTG + GTILE);

#pragma unroll
        for (int t = 0; t < 4; t++) {          // k8 steps
            uint32_t fa[2][4];
#pragma unroll
            for (int mt = 0; mt < 2; mt++) {
                int r0 = (wm * 32 + mt * 16 + g) * 36 + t * 8 + tig;
                int r1 = r0 + 8 * 36;
                fa[mt][0] = sA[r0]; fa[mt][1] = sA[r1];
                fa[mt][2] = sA[r0 + 4]; fa[mt][3] = sA[r1 + 4];
            }
#pragma unroll
            for (int nt = 0; nt < 8; nt++) {
                int n = (wn * 64 + nt * 8 + g) * 36 + t * 8 + tig;
                uint32_t fb[2] = { sB[n], sB[n + 4] };
                mmatf32(c_[0][nt], fa[0], fb);
                mmatf32(c_[1][nt], fa[1], fb);
            }
        }
        __syncthreads();
    }
#undef LOAD_STAGE

#pragma unroll
    for (int mt = 0; mt < 2; mt++) {
        int row0 = bm + wm * 32 + mt * 16 + g;
        int row1 = row0 + 8;
#pragma unroll
        for (int nt = 0; nt < 8; nt++) {
            int colc = wn * 64 + nt * 8 + tig * 2;   // 0..126 within CTA
            int col = bn + colc;
            int head = col >> 6;
            float b0 = bias[col], b1 = bias[col + 1];
            float x0 = c_[mt][nt][0] + b0, x1 = c_[mt][nt][1] + b1;
            float y0 = c_[mt][nt][2] + b0, y1 = c_[mt][nt][3] + b1;
            if (do_rope) {
                int i = (col & 63) >> 1;
                int pos0 = (((row0 & 1023) * 16 + head) & 1023);
                int pos1 = (((row1 & 1023) * 16 + head) & 1023);
                float2 cs0 = rope[pos0 * 32 + i];
                float2 cs1 = rope[pos1 * 32 + i];
                float t0 = x0 * cs0.x - x1 * cs0.y;
                x1 = x0 * cs0.y + x1 * cs0.x; x0 = t0;
                float t1 = y0 * cs1.x - y1 * cs1.y;
                y1 = y0 * cs1.y + y1 * cs1.x; y0 = t1;
            }
            x0 *= scale; x1 *= scale; y0 *= scale; y1 *= scale;
            if (round_out) {
                x0 = tf32r(x0); x1 = tf32r(x1); y0 = tf32r(y0); y1 = tf32r(y1);
            }
            *(float2*)&C[(size_t)row0 * 1024 + col] = make_float2(x0, x1);
            *(float2*)&C[(size_t)row1 * 1024 + col] = make_float2(y0, y1);
        }
    }
}

// Fused Q/K/V projections: blockIdx.z selects problem
__global__ void __launch_bounds__(256) qkv_gemm_kernel(
    const float* __restrict__ xr, const float* __restrict__ wt,
    const float* __restrict__ bq, const float* __restrict__ bk, const float* __restrict__ bv,
    float* __restrict__ pq, float* __restrict__ pk, float* __restrict__ pv,
    const float2* __restrict__ rope)
{
    extern __shared__ __align__(16) char dsm[];
    const size_t AD = (size_t)MT * DD;
    const size_t WD = (size_t)DD * DD;
    int z = blockIdx.z;
    const float* A = xr + z * AD;
    const float* B = wt + z * WD;
    const float* bias = (z == 0) ? bq : (z == 1) ? bk : bv;
    float* C = (z == 0) ? pq : (z == 1) ? pk : pv;
    gemm_body(A, B, bias, C, rope, (z < 2) ? 1 : 0, (z == 0) ? 0.125f : 1.0f, 1, dsm);
}

__global__ void __launch_bounds__(256) out_gemm_kernel(
    const float* __restrict__ A, const float* __restrict__ B,
    const float* __restrict__ bias, float* __restrict__ C)
{
    extern __shared__ __align__(16) char dsm[];
    gemm_body(A, B, bias, C, (const float2*)0, 0, 1.0f, 0, dsm);
}

// ---------------------------------------------------------------------------
// tf32 MMA flash attention: grid (16 qtiles, 16 h, 4 b), 128 thr (4 warps).
// Tiles 64x64 fp32, row stride 68 floats (272B) -> conflict-free fragments.
// Smem: Q + K0 K1 T0 T1 (double-buffered K/V^T) = 5 x 17408 = 87040 B.
// S = QK^T tf32 (64 mma/kt); P re-gathered to A-frag layout via shfl;
// PV tf32 (64 mma/kt). Output tf32-rounded fp32 for out-projection.
// ---------------------------------------------------------------------------
#define ATW 68
#define ATB 17408
#define ASMEM (5*ATB)   // 87040

__global__ void __launch_bounds__(128) attn_mma_kernel(
    const float* __restrict__ Q, const float* __restrict__ K,
    const float* __restrict__ T, float* __restrict__ O)
{
    extern __shared__ __align__(16) char sm_[];
    const uint32_t sb = smem_u32(sm_);
    const int tid  = threadIdx.x;
    const int lane = tid & 31;
    const int warp = tid >> 5;
    const int g = lane >> 2, tig = lane & 3;
    const int h = blockIdx.y, b = blockIdx.z;
    const int q0 = blockIdx.x * 64;
    const int z = b * 16 + h;

    const int lrow = tid >> 1;                 // 0..63
    const int lhf  = (tid & 1);                // half: 32 floats = 128B

    // ---- issue Q tile load (group 0) ----
    {
        const float* pq_ = Q + ((size_t)(b * 1024 + q0 + lrow)) * 1024 + h * 64 + lhf * 32;
        uint32_t d = sb + lrow * 272 + lhf * 128;
#pragma unroll
        for (int j = 0; j < 8; j++) cp16s(d + j * 16, pq_ + j * 4);
    }
    cp_commit();

#define LOAD_KT(kt, buf) do {                                                        \
        const float* pk_ = K + ((size_t)(b * 1024 + (kt) * 64 + lrow)) * 1024 + h * 64 + lhf * 32; \
        uint32_t dk = sb + (1 + 2 * (buf)) * ATB + lrow * 272 + lhf * 128;           \
        const float* pt_ = T + ((size_t)z * 64 + lrow) * 1024 + (kt) * 64 + lhf * 32; \
        uint32_t dt = sb + (2 + 2 * (buf)) * ATB + lrow * 272 + lhf * 128;           \
        _Pragma("unroll")                                                            \
        for (int j = 0; j < 8; j++) {                                                \
            cp16s(dk + j * 16, pk_ + j * 4);                                         \
            cp16s(dt + j * 16, pt_ + j * 4);                                         \
        }                                                                            \
    } while (0)

    LOAD_KT(0, 0);
    cp_commit();

    const uint32_t* sQ = (const uint32_t*)(sm_);

    // ---- Q ready: hoist fragments (8 k8-steps x 4 regs) ----
    cp_wait1();
    __syncthreads();
    uint32_t fq[8][4];
#pragma unroll
    for (int t = 0; t < 8; t++) {
        int r0 = (warp * 16 + g) * ATW + t * 8 + tig;
        int r1 = r0 + 8 * ATW;
        fq[t][0] = sQ[r0]; fq[t][1] = sQ[r1];
        fq[t][2] = sQ[r0 + 4]; fq[t][3] = sQ[r1 + 4];
    }

    float mA = -1e30f, mB = -1e30f, lA = 0.0f, lB = 0.0f;
    float o[8][4];
#pragma unroll
    for (int j = 0; j < 8; j++)
#pragma unroll
        for (int r = 0; r < 4; r++) o[j][r] = 0.0f;

    for (int kt = 0; kt < 16; kt++) {
        cp_wait0();
        __syncthreads();
        const int buf = kt & 1;
        if (kt + 1 < 16) { LOAD_KT(kt + 1, buf ^ 1); cp_commit(); }

        const uint32_t* sK = (const uint32_t*)(sm_ + (1 + 2 * buf) * ATB);
        const uint32_t* sT = (const uint32_t*)(sm_ + (2 + 2 * buf) * ATB);

        // ---- S = Q K^T ----
        float s[8][4];
#pragma unroll
        for (int j = 0; j < 8; j++)
#pragma unroll
            for (int r = 0; r < 4; r++) s[j][r] = 0.0f;
#pragma unroll
        for (int t = 0; t < 8; t++) {
#pragma unroll
            for (int j = 0; j < 8; j++) {
                int n = (j * 8 + g) * ATW + t * 8 + tig;
                uint32_t fk[2] = { sK[n], sK[n + 4] };
                mmatf32(s[j], fq[t], fk);
            }
        }

        // ---- online softmax (rows rA = warp*16+g, rB = rA+8) ----
        float mxA = -1e30f, mxB = -1e30f;
#pragma unroll
        for (int j = 0; j < 8; j++) {
            mxA = fmaxf(mxA, fmaxf(s[j][0], s[j][1]));
            mxB = fmaxf(mxB, fmaxf(s[j][2], s[j][3]));
        }
        mxA = fmaxf(mxA, __shfl_xor_sync(0xffffffffu, mxA, 1));
        mxA = fmaxf(mxA, __shfl_xor_sync(0xffffffffu, mxA, 2));
        mxB = fmaxf(mxB, __shfl_xor_sync(0xffffffffu, mxB, 1));
        mxB = fmaxf(mxB, __shfl_xor_sync(0xffffffffu, mxB, 2));
        float nmA = fmaxf(mA, mxA), nmB = fmaxf(mB, mxB);
        float corrA = __expf(mA - nmA), corrB = __expf(mB - nmB);
        float psA = 0.0f, psB = 0.0f;
#pragma unroll
        for (int j = 0; j < 8; j++) {
            s[j][0] = __expf(s[j][0] - nmA); psA += s[j][0];
            s[j][1] = __expf(s[j][1] - nmA); psA += s[j][1];
            s[j][2] = __expf(s[j][2] - nmB); psB += s[j][2];
            s[j][3] = __expf(s[j][3] - nmB); psB += s[j][3];
        }
        psA += __shfl_xor_sync(0xffffffffu, psA, 1);
        psA += __shfl_xor_sync(0xffffffffu, psA, 2);
        psB += __shfl_xor_sync(0xffffffffu, psB, 1);
        psB += __shfl_xor_sync(0xffffffffu, psB, 2);
        lA = lA * corrA + psA; mA = nmA;
        lB = lB * corrB + psB; mB = nmB;
#pragma unroll
        for (int j = 0; j < 8; j++) {
            o[j][0] *= corrA; o[j][1] *= corrA;
            o[j][2] *= corrB; o[j][3] *= corrB;
        }

        // ---- PV: re-gather P into tf32 A-frag layout via shfl, then mma ----
        // P[rowA=g][col u*8+c] lives in lane (g*4 + c/2), reg (c&1); rows g+8 in regs 2|(c&1).
#pragma unroll
        for (int u = 0; u < 8; u++) {          // k8 step over keys
            int src1 = (lane & ~3) + (tig >> 1);       // owner of col u*8+tig
            int src2 = src1 + 2;                       // owner of col u*8+tig+4
            float x0 = __shfl_sync(0xffffffffu, s[u][0], src1);
            float x1 = __shfl_sync(0xffffffffu, s[u][1], src1);
            float x2 = __shfl_sync(0xffffffffu, s[u][2], src1);
            float x3 = __shfl_sync(0xffffffffu, s[u][3], src1);
            float y0 = __shfl_sync(0xffffffffu, s[u][0], src2);
            float y1 = __shfl_sync(0xffffffffu, s[u][1], src2);
            float y2 = __shfl_sync(0xffffffffu, s[u][2], src2);
            float y3 = __shfl_sync(0xffffffffu, s[u][3], src2);
            bool odd = (tig & 1);
            uint32_t pa[4];
            pa[0] = __float_as_uint(tf32r(odd ? x1 : x0));   // P[g][u8+tig]
            pa[1] = __float_as_uint(tf32r(odd ? x3 : x2));   // P[g+8][u8+tig]
            pa[2] = __float_as_uint(tf32r(odd ? y1 : y0));   // P[g][u8+tig+4]
            pa[3] = __float_as_uint(tf32r(odd ? y3 : y2));   // P[g+8][u8+tig+4]
#pragma unroll
            for (int j = 0; j < 8; j++) {
                int n = (j * 8 + g) * ATW + u * 8 + tig;
                uint32_t fv[2] = { sT[n], sT[n + 4] };
                mmatf32(o[j], pa, fv);
            }
        }
    }
#undef LOAD_KT

    // ---- epilogue: normalize, round, store fp32 ----
    float invA = 1.0f / lA, invB = 1.0f / lB;
    const size_t tokA = (size_t)(b * 1024 + q0 + warp * 16 + g);
    const size_t tokB = tokA + 8;
#pragma unroll
    for (int j = 0; j < 8; j++) {
        int col = h * 64 + j * 8 + tig * 2;
        *(float2*)&O[tokA * 1024 + col] =
            make_float2(tf32r(o[j][0] * invA), tf32r(o[j][1] * invA));
        *(float2*)&O[tokB * 1024 + col] =
            make_float2(tf32r(o[j][2] * invB), tf32r(o[j][3] * invB));
    }
}

// ---------------------------------------------------------------------------
extern "C" void kernel_launch(void* const* d_in, const int* in_sizes, int n_in,
                              void* d_out, int out_size)
{
    const float* q  = (const float*)d_in[0];
    const float* k  = (const float*)d_in[1];
    const float* v  = (const float*)d_in[2];
    const float* Wq = (const float*)d_in[3];
    const float* bq = (const float*)d_in[4];
    const float* Wk = (const float*)d_in[5];
    const float* bk = (const float*)d_in[6];
    const float* Wv = (const float*)d_in[7];
    const float* bv = (const float*)d_in[8];
    const float* Wo = (const float*)d_in[9];
    const float* bo = (const float*)d_in[10];
    float* out = (float*)d_out;

    float2* gr; cudaGetSymbolAddress((void**)&gr, g_rope);
    float* gx; cudaGetSymbolAddress((void**)&gx, g_x);
    float* gw; cudaGetSymbolAddress((void**)&gw, g_wt);
    float* pq; cudaGetSymbolAddress((void**)&pq, g_pq);
    float* pk; cudaGetSymbolAddress((void**)&pk, g_pk);
    float* pv; cudaGetSymbolAddress((void**)&pv, g_pv);
    float* vt; cudaGetSymbolAddress((void**)&vt, g_vt);

    cudaFuncSetAttribute(qkv_gemm_kernel, cudaFuncAttributeMaxDynamicSharedMemorySize, GSMEM);
    cudaFuncSetAttribute(out_gemm_kernel, cudaFuncAttributeMaxDynamicSharedMemorySize, GSMEM);
    cudaFuncSetAttribute(attn_mma_kernel, cudaFuncAttributeMaxDynamicSharedMemorySize, ASMEM);

    const size_t AD = (size_t)MT * DD;
    const size_t WD = (size_t)DD * DD;

    // 0) RoPE table + weight transpose/round + input rounds
    rope_table_kernel<<<1024 * 32 / 256, 256>>>(gr);
    convw_kernel<<<dim3(32, 32, 4), 256>>>(Wq, Wk, Wv, Wo, gw);
    round_kernel<<<dim3(AD / 1024, 1, 3), 256>>>(q, k, v, gx);

    // 1) fused Q/K/V projections (tf32 MMA; RoPE + scale fused; outputs rounded)
    dim3 ggrid(8, 32, 3);
    qkv_gemm_kernel<<<ggrid, 256, GSMEM>>>(gx, gw, bq, bk, bv, pq, pk, pv, gr);

    // 2) transpose V for attention B-operand
    transv_kernel<<<dim3(32, 2, 64), 256>>>(pv, vt);

    // 3) tf32 mma attention -> rounded fp32 into g_x slot 0
    dim3 agrid(16, NH, NB);
    attn_mma_kernel<<<agrid, 128, ASMEM>>>(pq, pk, vt, gx);

    // 4) output projection -> fp32 d_out
    dim3 ogrid(8, 32, 1);
    out_gemm_kernel<<<ogrid, 256, GSMEM>>>(gx, gw + 3 * WD, bo, out);
}

// round 17
// speedup vs baseline: 2.7193x; 1.1390x over previous
#include <cuda_runtime.h>
#include <stdint.h>
#include <math.h>

#define NB 4
#define SS 1024
#define DD 1024
#define NH 16
#define MT (NB*SS)   // 4096 rows

// ---------------------------------------------------------------------------
// Scratch (__device__ globals; no allocation allowed). All fp32, tf32-rounded.
// ---------------------------------------------------------------------------
__device__ float2 g_rope[1024*32];     // [pos][freq] -> (cos,sin)
__device__ float g_x[3][MT*DD];        // rounded inputs q,k,v; slot0 reused for attn-out
__device__ float g_wt[4][DD*DD];       // weights transposed [n][k], tf32-rounded
__device__ float g_pq[MT*DD];          // projected Q (rope, x0.125)
__device__ float g_pk[MT*DD];          // projected K (rope)
__device__ float g_pv[MT*DD];          // projected V
__device__ float g_vt[MT*DD];          // V transposed: [(b*16+h)*64+d][token]

// ---------------------------------------------------------------------------
// helpers
// ---------------------------------------------------------------------------
__device__ __forceinline__ void cp16s(uint32_t s, const void* g) {
    asm volatile("cp.async.ca.shared.global [%0], [%1], 16;\n" :: "r"(s), "l"(g));
}
__device__ __forceinline__ void cp_commit() { asm volatile("cp.async.commit_group;\n"); }
__device__ __forceinline__ void cp_wait0()  { asm volatile("cp.async.wait_group 0;\n"); }
__device__ __forceinline__ uint32_t smem_u32(const void* p) {
    uint32_t a;
    asm("{ .reg .u64 t; cvta.to.shared.u64 t, %1; cvt.u32.u64 %0, t; }" : "=r"(a) : "l"(p));
    return a;
}
// round fp32 -> tf32 (rne on 10-bit mantissa), returned as fp32 bits
__device__ __forceinline__ float tf32r(float x) {
    uint32_t r;
    asm("cvt.rna.tf32.f32 %0, %1;" : "=r"(r) : "f"(x));
    return __uint_as_float(r);
}
// Warp MMA: D(m16n8) += A(m16k8,row) * B(k8n8,col)  tf32 in, f32 accum
__device__ __forceinline__ void mmatf32(float* c, const uint32_t* a, const uint32_t* b) {
    asm volatile("mma.sync.aligned.m16n8k8.row.col.f32.tf32.tf32.f32 "
        "{%0,%1,%2,%3}, {%4,%5,%6,%7}, {%8,%9}, {%0,%1,%2,%3};"
        : "+f"(c[0]), "+f"(c[1]), "+f"(c[2]), "+f"(c[3])
        : "r"(a[0]), "r"(a[1]), "r"(a[2]), "r"(a[3]), "r"(b[0]), "r"(b[1]));
}

// ---------------------------------------------------------------------------
// RoPE table (reference quirk: pos = (s*16+h) & 1023 applied at use site)
// ---------------------------------------------------------------------------
__global__ __launch_bounds__(256) void rope_table_kernel(float2* __restrict__ tab)
{
    int idx = blockIdx.x * 256 + threadIdx.x;
    int i = idx & 31;
    int pos = idx >> 5;
    const double LOG1E4 = 9.210340371976184;
    double inv = exp(-((double)i / 32.0) * LOG1E4);
    double ang = (double)pos * inv;
    tab[idx] = make_float2((float)cos(ang), (float)sin(ang));
}

// ---------------------------------------------------------------------------
// Round inputs to tf32 (q,k,v via blockIdx.z)
// ---------------------------------------------------------------------------
__global__ __launch_bounds__(256) void round_kernel(
    const float* __restrict__ q, const float* __restrict__ k, const float* __restrict__ v,
    float* __restrict__ dst_base)
{
    const size_t AD = (size_t)MT * DD;
    const float* src = (blockIdx.z == 0) ? q : (blockIdx.z == 1) ? k : v;
    float* dst = dst_base + blockIdx.z * AD;
    int i = (blockIdx.x * 256 + threadIdx.x) * 4;
    float4 a = *(const float4*)&src[i];
    a.x = tf32r(a.x); a.y = tf32r(a.y); a.z = tf32r(a.z); a.w = tf32r(a.w);
    *(float4*)&dst[i] = a;
}

// ---------------------------------------------------------------------------
// Transpose + round weights: W[k][n] -> Wt[n][k] (tf32-rounded)
// ---------------------------------------------------------------------------
__global__ __launch_bounds__(256) void convw_kernel(
    const float* __restrict__ Wq, const float* __restrict__ Wk,
    const float* __restrict__ Wv, const float* __restrict__ Wo,
    float* __restrict__ wt)
{
    __shared__ float t[32][33];
    const float* W = (blockIdx.z == 0) ? Wq : (blockIdx.z == 1) ? Wk : (blockIdx.z == 2) ? Wv : Wo;
    float* o = wt + (size_t)blockIdx.z * DD * DD;
    int n0 = blockIdx.x * 32, k0 = blockIdx.y * 32;
    int tx = threadIdx.x & 31, ty = threadIdx.x >> 5;
#pragma unroll
    for (int r = 0; r < 32; r += 8)
        t[ty + r][tx] = W[(size_t)(k0 + ty + r) * DD + n0 + tx];
    __syncthreads();
#pragma unroll
    for (int r = 0; r < 32; r += 8)
        o[(size_t)(n0 + ty + r) * DD + k0 + tx] = tf32r(t[tx][ty + r]);
}

// ---------------------------------------------------------------------------
// Transpose projected V: [token][h*64+d] -> [(b*16+h)*64+d][token]
// ---------------------------------------------------------------------------
__global__ __launch_bounds__(256) void transv_kernel(
    const float* __restrict__ V, float* __restrict__ T)
{
    __shared__ float t[32][33];
    int z = blockIdx.z;            // b*16+h
    int b = z >> 4, h = z & 15;
    int s0 = blockIdx.x * 32, d0 = blockIdx.y * 32;
    int tx = threadIdx.x & 31, ty = threadIdx.x >> 5;
#pragma unroll
    for (int r = 0; r < 32; r += 8)
        t[ty + r][tx] = V[(size_t)(b * 1024 + s0 + ty + r) * 1024 + h * 64 + d0 + tx];
    __syncthreads();
#pragma unroll
    for (int r = 0; r < 32; r += 8)
        T[((size_t)z * 64 + d0 + ty + r) * 1024 + s0 + tx] = t[tx][ty + r];
}

// ---------------------------------------------------------------------------
// tf32 warp-MMA GEMM. CTA 128(M) x 128(N = 2 heads). 256 thr, 8 warps 4Mx2N,
// warp tile 32x64. K chunks of 32, 2-stage cp.async, ONE barrier per chunk
// (load issued after top barrier -> overwrite distance-2 safe).
// Smem rows: 32 floats padded to 36. Stage = 36864; double = 73728.
// ---------------------------------------------------------------------------
#define GTILE 18432
#define GSTG  (2*GTILE)
#define GSMEM (2*GSTG)   // 73728

__device__ __forceinline__ void gemm_body(
    const float* __restrict__ A, const float* __restrict__ B,
    const float* __restrict__ bias,
    float* __restrict__ C, const float2* __restrict__ rope,
    int do_rope, float scale, int round_out, char* dsm)
{
    const uint32_t sb = smem_u32(dsm);
    const int tid  = threadIdx.x;
    const int lane = tid & 31;
    const int warp = tid >> 5;
    const int wm = warp >> 1, wn = warp & 1;
    const int g = lane >> 2, tig = lane & 3;
    const int bm = blockIdx.y * 128;
    const int bn = blockIdx.x * 128;

    const int lr   = tid >> 1;         // 0..127
    const int lhf  = (tid & 1);        // half: 16 floats = 64B

#define LOAD_STAGE(c, buf) do {                                                   \
        uint32_t base = sb + (buf) * GSTG;                                        \
        int k0 = (c) * 32;                                                        \
        const float* pa = A + (size_t)(bm + lr) * 1024 + k0 + lhf * 16;           \
        uint32_t ao = base + (uint32_t)lr * 144u + (uint32_t)lhf * 64u;           \
        cp16s(ao,      pa);                                                       \
        cp16s(ao + 16, pa + 4);                                                   \
        cp16s(ao + 32, pa + 8);                                                   \
        cp16s(ao + 48, pa + 12);                                                  \
        const float* pb = B + (size_t)(bn + lr) * 1024 + k0 + lhf * 16;           \
        uint32_t bo = base + GTILE + (uint32_t)lr * 144u + (uint32_t)lhf * 64u;   \
        cp16s(bo,      pb);                                                       \
        cp16s(bo + 16, pb + 4);                                                   \
        cp16s(bo + 32, pb + 8);                                                   \
        cp16s(bo + 48, pb + 12);                                                  \
    } while (0)

    float c_[2][8][4];
#pragma unroll
    for (int mt = 0; mt < 2; mt++)
#pragma unroll
        for (int nt = 0; nt < 8; nt++)
#pragma unroll
            for (int r = 0; r < 4; r++) c_[mt][nt][r] = 0.0f;

    LOAD_STAGE(0, 0);
    cp_commit();

    for (int c = 0; c < 32; c++) {
        cp_wait0();            // stage c arrived (overlapped with compute of c-1)
        __syncthreads();       // also: all warps done reading buf (c-1)&1
        if (c + 1 < 32) { LOAD_STAGE(c + 1, (c + 1) & 1); cp_commit(); }

        const uint32_t* sA = (const uint32_t*)(dsm + (c & 1) * GSTG);
        const uint32_t* sB = (const uint32_t*)(dsm + (c & 1) * GSTG + GTILE);

#pragma unroll
        for (int t = 0; t < 4; t++) {          // k8 steps
            uint32_t fa[2][4];
#pragma unroll
            for (int mt = 0; mt < 2; mt++) {
                int r0 = (wm * 32 + mt * 16 + g) * 36 + t * 8 + tig;
                int r1 = r0 + 8 * 36;
                fa[mt][0] = sA[r0]; fa[mt][1] = sA[r1];
                fa[mt][2] = sA[r0 + 4]; fa[mt][3] = sA[r1 + 4];
            }
#pragma unroll
            for (int nt = 0; nt < 8; nt++) {
                int n = (wn * 64 + nt * 8 + g) * 36 + t * 8 + tig;
                uint32_t fb[2] = { sB[n], sB[n + 4] };
                mmatf32(c_[0][nt], fa[0], fb);
                mmatf32(c_[1][nt], fa[1], fb);
            }
        }
    }
#undef LOAD_STAGE

#pragma unroll
    for (int mt = 0; mt < 2; mt++) {
        int row0 = bm + wm * 32 + mt * 16 + g;
        int row1 = row0 + 8;
#pragma unroll
        for (int nt = 0; nt < 8; nt++) {
            int col = bn + wn * 64 + nt * 8 + tig * 2;
            int head = col >> 6;
            float b0 = bias[col], b1 = bias[col + 1];
            float x0 = c_[mt][nt][0] + b0, x1 = c_[mt][nt][1] + b1;
            float y0 = c_[mt][nt][2] + b0, y1 = c_[mt][nt][3] + b1;
            if (do_rope) {
                int i = (col & 63) >> 1;
                int pos0 = (((row0 & 1023) * 16 + head) & 1023);
                int pos1 = (((row1 & 1023) * 16 + head) & 1023);
                float2 cs0 = rope[pos0 * 32 + i];
                float2 cs1 = rope[pos1 * 32 + i];
                float t0 = x0 * cs0.x - x1 * cs0.y;
                x1 = x0 * cs0.y + x1 * cs0.x; x0 = t0;
                float t1 = y0 * cs1.x - y1 * cs1.y;
                y1 = y0 * cs1.y + y1 * cs1.x; y0 = t1;
            }
            x0 *= scale; x1 *= scale; y0 *= scale; y1 *= scale;
            if (round_out) {
                x0 = tf32r(x0); x1 = tf32r(x1); y0 = tf32r(y0); y1 = tf32r(y1);
            }
            *(float2*)&C[(size_t)row0 * 1024 + col] = make_float2(x0, x1);
            *(float2*)&C[(size_t)row1 * 1024 + col] = make_float2(y0, y1);
        }
    }
}

// Fused Q/K/V projections: blockIdx.z selects problem
__global__ void __launch_bounds__(256) qkv_gemm_kernel(
    const float* __restrict__ xr, const float* __restrict__ wt,
    const float* __restrict__ bq, const float* __restrict__ bk, const float* __restrict__ bv,
    float* __restrict__ pq, float* __restrict__ pk, float* __restrict__ pv,
    const float2* __restrict__ rope)
{
    extern __shared__ __align__(16) char dsm[];
    const size_t AD = (size_t)MT * DD;
    const size_t WD = (size_t)DD * DD;
    int z = blockIdx.z;
    const float* A = xr + z * AD;
    const float* B = wt + z * WD;
    const float* bias = (z == 0) ? bq : (z == 1) ? bk : bv;
    float* C = (z == 0) ? pq : (z == 1) ? pk : pv;
    gemm_body(A, B, bias, C, rope, (z < 2) ? 1 : 0, (z == 0) ? 0.125f : 1.0f, 1, dsm);
}

__global__ void __launch_bounds__(256) out_gemm_kernel(
    const float* __restrict__ A, const float* __restrict__ B,
    const float* __restrict__ bias, float* __restrict__ C)
{
    extern __shared__ __align__(16) char dsm[];
    gemm_body(A, B, bias, C, (const float2*)0, 0, 1.0f, 0, dsm);
}

// ---------------------------------------------------------------------------
// tf32 MMA flash attention: grid (8 qtiles, 16 h, 4 b), 256 thr (8 warps).
// CTA covers 128 q-rows; warp w owns rows w*16..w*16+15. K tiles 64x64.
// Smem: Q(128x68) + K0 K1 T0 T1 (64x68 each) = 34816 + 4*17408 = 104448 B
// -> 2 CTAs/SM = 16 warps. Q fragments re-read from smem per key-tile
// (keeps regs ~100). One barrier per key-tile.
// ---------------------------------------------------------------------------
#define ATW 68
#define ATB 17408
#define AQB 34816
#define ASMEM (AQB + 4*ATB)   // 104448

__global__ void __launch_bounds__(256) attn_mma_kernel(
    const float* __restrict__ Q, const float* __restrict__ K,
    const float* __restrict__ T, float* __restrict__ O)
{
    extern __shared__ __align__(16) char sm_[];
    const uint32_t sb = smem_u32(sm_);
    const int tid  = threadIdx.x;
    const int lane = tid & 31;
    const int warp = tid >> 5;                 // 0..7
    const int g = lane >> 2, tig = lane & 3;
    const int h = blockIdx.y, b = blockIdx.z;
    const int q0 = blockIdx.x * 128;
    const int z = b * 16 + h;

    // ---- issue Q tile load (128 rows; each thread half a row) ----
    {
        const int lrow = tid >> 1;             // 0..127
        const int lhf  = (tid & 1);
        const float* pq_ = Q + ((size_t)(b * 1024 + q0 + lrow)) * 1024 + h * 64 + lhf * 32;
        uint32_t d = sb + lrow * 272 + lhf * 128;
#pragma unroll
        for (int j = 0; j < 8; j++) cp16s(d + j * 16, pq_ + j * 4);
    }

    // K/T tiles: 64 rows; each thread a quarter row (16 floats)
    const int krow = tid >> 2;                 // 0..63
    const int kq   = (tid & 3);                // quarter

#define LOAD_KT(kt, buf) do {                                                        \
        const float* pk_ = K + ((size_t)(b * 1024 + (kt) * 64 + krow)) * 1024 + h * 64 + kq * 16; \
        uint32_t dk = sb + AQB + (buf) * ATB + krow * 272 + kq * 64;                 \
        const float* pt_ = T + ((size_t)z * 64 + krow) * 1024 + (kt) * 64 + kq * 16; \
        uint32_t dt = sb + AQB + 2 * ATB + (buf) * ATB + krow * 272 + kq * 64;       \
        _Pragma("unroll")                                                            \
        for (int j = 0; j < 4; j++) {                                                \
            cp16s(dk + j * 16, pk_ + j * 4);                                         \
            cp16s(dt + j * 16, pt_ + j * 4);                                         \
        }                                                                            \
    } while (0)

    LOAD_KT(0, 0);
    cp_commit();

    const uint32_t* sQ = (const uint32_t*)(sm_);

    float mA = -1e30f, mB = -1e30f, lA = 0.0f, lB = 0.0f;
    float o[8][4];
#pragma unroll
    for (int j = 0; j < 8; j++)
#pragma unroll
        for (int r = 0; r < 4; r++) o[j][r] = 0.0f;

    for (int kt = 0; kt < 16; kt++) {
        cp_wait0();
        __syncthreads();       // K/T(kt) visible; all warps done with buf (kt-1)&1
        const int buf = kt & 1;
        if (kt + 1 < 16) { LOAD_KT(kt + 1, buf ^ 1); cp_commit(); }

        const uint32_t* sK = (const uint32_t*)(sm_ + AQB + buf * ATB);
        const uint32_t* sT = (const uint32_t*)(sm_ + AQB + 2 * ATB + buf * ATB);

        // ---- S = Q K^T ----
        float s[8][4];
#pragma unroll
        for (int j = 0; j < 8; j++)
#pragma unroll
            for (int r = 0; r < 4; r++) s[j][r] = 0.0f;
#pragma unroll
        for (int t = 0; t < 8; t++) {
            uint32_t fq[4];
            int r0 = (warp * 16 + g) * ATW + t * 8 + tig;
            int r1 = r0 + 8 * ATW;
            fq[0] = sQ[r0]; fq[1] = sQ[r1];
            fq[2] = sQ[r0 + 4]; fq[3] = sQ[r1 + 4];
#pragma unroll
            for (int j = 0; j < 8; j++) {
                int n = (j * 8 + g) * ATW + t * 8 + tig;
                uint32_t fk[2] = { sK[n], sK[n + 4] };
                mmatf32(s[j], fq, fk);
            }
        }

        // ---- online softmax (rows rA = warp*16+g, rB = rA+8) ----
        float mxA = -1e30f, mxB = -1e30f;
#pragma unroll
        for (int j = 0; j < 8; j++) {
            mxA = fmaxf(mxA, fmaxf(s[j][0], s[j][1]));
            mxB = fmaxf(mxB, fmaxf(s[j][2], s[j][3]));
        }
        mxA = fmaxf(mxA, __shfl_xor_sync(0xffffffffu, mxA, 1));
        mxA = fmaxf(mxA, __shfl_xor_sync(0xffffffffu, mxA, 2));
        mxB = fmaxf(mxB, __shfl_xor_sync(0xffffffffu, mxB, 1));
        mxB = fmaxf(mxB, __shfl_xor_sync(0xffffffffu, mxB, 2));
        float nmA = fmaxf(mA, mxA), nmB = fmaxf(mB, mxB);
        float corrA = __expf(mA - nmA), corrB = __expf(mB - nmB);
        float psA = 0.0f, psB = 0.0f;
#pragma unroll
        for (int j = 0; j < 8; j++) {
            s[j][0] = __expf(s[j][0] - nmA); psA += s[j][0];
            s[j][1] = __expf(s[j][1] - nmA); psA += s[j][1];
            s[j][2] = __expf(s[j][2] - nmB); psB += s[j][2];
            s[j][3] = __expf(s[j][3] - nmB); psB += s[j][3];
        }
        psA += __shfl_xor_sync(0xffffffffu, psA, 1);
        psA += __shfl_xor_sync(0xffffffffu, psA, 2);
        psB += __shfl_xor_sync(0xffffffffu, psB, 1);
        psB += __shfl_xor_sync(0xffffffffu, psB, 2);
        lA = lA * corrA + psA; mA = nmA;
        lB = lB * corrB + psB; mB = nmB;
#pragma unroll
        for (int j = 0; j < 8; j++) {
            o[j][0] *= corrA; o[j][1] *= corrA;
            o[j][2] *= corrB; o[j][3] *= corrB;
        }

        // ---- PV: re-gather P into tf32 A-frag layout via shfl, then mma ----
#pragma unroll
        for (int u = 0; u < 8; u++) {
            int src1 = (lane & ~3) + (tig >> 1);
            int src2 = src1 + 2;
            float x0 = __shfl_sync(0xffffffffu, s[u][0], src1);
            float x1 = __shfl_sync(0xffffffffu, s[u][1], src1);
            float x2 = __shfl_sync(0xffffffffu, s[u][2], src1);
            float x3 = __shfl_sync(0xffffffffu, s[u][3], src1);
            float y0 = __shfl_sync(0xffffffffu, s[u][0], src2);
            float y1 = __shfl_sync(0xffffffffu, s[u][1], src2);
            float y2 = __shfl_sync(0xffffffffu, s[u][2], src2);
            float y3 = __shfl_sync(0xffffffffu, s[u][3], src2);
            bool odd = (tig & 1);
            uint32_t pa[4];
            pa[0] = __float_as_uint(tf32r(odd ? x1 : x0));
            pa[1] = __float_as_uint(tf32r(odd ? x3 : x2));
            pa[2] = __float_as_uint(tf32r(odd ? y1 : y0));
            pa[3] = __float_as_uint(tf32r(odd ? y3 : y2));
#pragma unroll
            for (int j = 0; j < 8; j++) {
                int n = (j * 8 + g) * ATW + u * 8 + tig;
                uint32_t fv[2] = { sT[n], sT[n + 4] };
                mmatf32(o[j], pa, fv);
            }
        }
    }
#undef LOAD_KT

    // ---- epilogue: normalize, round, store fp32 ----
    float invA = 1.0f / lA, invB = 1.0f / lB;
    const size_t tokA = (size_t)(b * 1024 + q0 + warp * 16 + g);
    const size_t tokB = tokA + 8;
#pragma unroll
    for (int j = 0; j < 8; j++) {
        int col = h * 64 + j * 8 + tig * 2;
        *(float2*)&O[tokA * 1024 + col] =
            make_float2(tf32r(o[j][0] * invA), tf32r(o[j][1] * invA));
        *(float2*)&O[tokB * 1024 + col] =
            make_float2(tf32r(o[j][2] * invB), tf32r(o[j][3] * invB));
    }
}

// ---------------------------------------------------------------------------
extern "C" void kernel_launch(void* const* d_in, const int* in_sizes, int n_in,
                              void* d_out, int out_size)
{
    const float* q  = (const float*)d_in[0];
    const float* k  = (const float*)d_in[1];
    const float* v  = (const float*)d_in[2];
    const float* Wq = (const float*)d_in[3];
    const float* bq = (const float*)d_in[4];
    const float* Wk = (const float*)d_in[5];
    const float* bk = (const float*)d_in[6];
    const float* Wv = (const float*)d_in[7];
    const float* bv = (const float*)d_in[8];
    const float* Wo = (const float*)d_in[9];
    const float* bo = (const float*)d_in[10];
    float* out = (float*)d_out;

    float2* gr; cudaGetSymbolAddress((void**)&gr, g_rope);
    float* gx; cudaGetSymbolAddress((void**)&gx, g_x);
    float* gw; cudaGetSymbolAddress((void**)&gw, g_wt);
    float* pq; cudaGetSymbolAddress((void**)&pq, g_pq);
    float* pk; cudaGetSymbolAddress((void**)&pk, g_pk);
    float* pv; cudaGetSymbolAddress((void**)&pv, g_pv);
    float* vt; cudaGetSymbolAddress((void**)&vt, g_vt);

    cudaFuncSetAttribute(qkv_gemm_kernel, cudaFuncAttributeMaxDynamicSharedMemorySize, GSMEM);
    cudaFuncSetAttribute(out_gemm_kernel, cudaFuncAttributeMaxDynamicSharedMemorySize, GSMEM);
    cudaFuncSetAttribute(attn_mma_kernel, cudaFuncAttributeMaxDynamicSharedMemorySize, ASMEM);

    const size_t AD = (size_t)MT * DD;
    const size_t WD = (size_t)DD * DD;

    // 0) RoPE table + weight transpose/round + input rounds
    rope_table_kernel<<<1024 * 32 / 256, 256>>>(gr);
    convw_kernel<<<dim3(32, 32, 4), 256>>>(Wq, Wk, Wv, Wo, gw);
    round_kernel<<<dim3(AD / 1024, 1, 3), 256>>>(q, k, v, gx);

    // 1) fused Q/K/V projections (tf32 MMA; RoPE + scale fused; outputs rounded)
    dim3 ggrid(8, 32, 3);
    qkv_gemm_kernel<<<ggrid, 256, GSMEM>>>(gx, gw, bq, bk, bv, pq, pk, pv, gr);

    // 2) transpose V for attention B-operand
    transv_kernel<<<dim3(32, 2, 64), 256>>>(pv, vt);

    // 3) tf32 mma attention -> rounded fp32 into g_x slot 0
    dim3 agrid(8, NH, NB);
    attn_mma_kernel<<<agrid, 256, ASMEM>>>(pq, pk, vt, gx);

    // 4) output projection -> fp32 d_out
    dim3 ogrid(8, 32, 1);
    out_gemm_kernel<<<ogrid, 256, GSMEM>>>(gx, gw + 3 * WD, bo, out);
}